// round 3
// baseline (speedup 1.0000x reference)
#include <cuda_runtime.h>
#include <math.h>

// ---------------- model dims ----------------
#define NLAYER 4
#define DMODEL 1024
#define NHEAD  16
#define DHEAD  64
#define NTOK   1536
#define NCTX   512
#define VOCAB  8192
#define FFI    2730          // GEGLU inner
#define FF2    5460          // 2*FFI

// ---------------- scratch (device globals; no allocation allowed) ----------------
__device__ float g_H  [NTOK * DMODEL];
__device__ float g_CTX[NCTX * DMODEL];
__device__ float g_XN [NTOK * DMODEL];
__device__ float g_Q  [NTOK * DMODEL];
__device__ float g_KV [NTOK * 2 * DMODEL];
__device__ float g_QN [NHEAD * NTOK * DHEAD];
__device__ float g_K  [NHEAD * (NTOK + 1) * DHEAD];
__device__ float g_V  [NHEAD * (NTOK + 1) * DHEAD];
__device__ float g_O  [NTOK * DMODEL];
__device__ float g_HH [NTOK * FF2];
__device__ float g_GN [NTOK * FFI];

// ---------------- f32x2 packed-FMA helpers (2x FFMA throughput on sm_103a) ----------------
__device__ __forceinline__ unsigned long long bcast2(float x) {
    unsigned long long r; unsigned u = __float_as_uint(x);
    asm("mov.b64 %0, {%1, %1};" : "=l"(r) : "r"(u));
    return r;
}
__device__ __forceinline__ void fma2(unsigned long long& d, unsigned long long a, unsigned long long b) {
    asm("fma.rn.f32x2 %0, %1, %2, %0;" : "+l"(d) : "l"(a), "l"(b));
}
__device__ __forceinline__ float2 unpack2(unsigned long long v) {
    unsigned lo, hi;
    asm("mov.b64 {%0, %1}, %2;" : "=r"(lo), "=r"(hi) : "l"(v));
    float2 r; r.x = __uint_as_float(lo); r.y = __uint_as_float(hi);
    return r;
}

// ---------------- embeddings ----------------
__global__ void embed_img_kernel(const int* __restrict__ ids, const float* __restrict__ te,
                                 const float* __restrict__ pe, float* __restrict__ out) {
    int i = blockIdx.x * blockDim.x + threadIdx.x;
    if (i >= NTOK * DMODEL) return;
    int n = i >> 10, d = i & 1023;
    out[i] = te[(size_t)ids[n] * DMODEL + d] + pe[i];
}
__global__ void embed_ctx_kernel(const int* __restrict__ ids, const float* __restrict__ te,
                                 const float* __restrict__ pe, float* __restrict__ out) {
    int i = blockIdx.x * blockDim.x + threadIdx.x;
    if (i >= NCTX * DMODEL) return;
    int n = i >> 10, d = i & 1023;
    out[i] = te[(size_t)ids[n] * DMODEL + d] + pe[i];
}

// ---------------- LayerNorm (one block per row, 256 threads) ----------------
__global__ void ln_kernel(const float* __restrict__ X, const float* __restrict__ g,
                          float* __restrict__ Y, int C) {
    int row = blockIdx.x;
    const float* x = X + (size_t)row * C;
    float* y = Y + (size_t)row * C;
    int tid = threadIdx.x;
    float s1 = 0.f, s2 = 0.f;
    for (int c = tid; c < C; c += 256) { float v = x[c]; s1 += v; s2 += v * v; }
    __shared__ float red[512];
    red[tid] = s1; red[256 + tid] = s2;
    __syncthreads();
    for (int s = 128; s > 0; s >>= 1) {
        if (tid < s) { red[tid] += red[tid + s]; red[256 + tid] += red[256 + tid + s]; }
        __syncthreads();
    }
    float mean = red[0] / C;
    float var  = red[256] / C - mean * mean;
    float inv  = rsqrtf(var + 1e-5f);
    for (int c = tid; c < C; c += 256) y[c] = (x[c] - mean) * inv * g[c];
}

// ---------------- fused GEGLU + LayerNorm ----------------
__global__ void geglu_ln_kernel(const float* __restrict__ HH, const float* __restrict__ g2,
                                float* __restrict__ Y) {
    int row = blockIdx.x;
    const float* h = HH + (size_t)row * FF2;
    float* y = Y + (size_t)row * FFI;
    int tid = threadIdx.x;
    __shared__ float buf[FFI];
    __shared__ float red[512];
    float s1 = 0.f, s2 = 0.f;
    for (int c = tid; c < FFI; c += 256) {
        float a = h[c], gate = h[FFI + c];
        float v = gate * (0.5f * a * (1.0f + erff(a * 0.70710678118654752f)));  // exact gelu
        buf[c] = v; s1 += v; s2 += v * v;
    }
    red[tid] = s1; red[256 + tid] = s2;
    __syncthreads();
    for (int s = 128; s > 0; s >>= 1) {
        if (tid < s) { red[tid] += red[tid + s]; red[256 + tid] += red[256 + tid + s]; }
        __syncthreads();
    }
    float mean = red[0] / FFI;
    float var  = red[256] / FFI - mean * mean;
    float inv  = rsqrtf(var + 1e-5f);
    for (int c = tid; c < FFI; c += 256) y[c] = (buf[c] - mean) * inv * g2[c];
}

// ---------------- Q prep: l2norm * qs * SCALE, layout [H][Nq][64] ----------------
__global__ void prep_q_kernel(const float* __restrict__ Qin, const float* __restrict__ qs,
                              float* __restrict__ QN, int Nq) {
    int gw = (blockIdx.x * blockDim.x + threadIdx.x) >> 5;
    int lane = threadIdx.x & 31;
    if (gw >= NHEAD * Nq) return;
    int h = gw / Nq, n = gw % Nq;
    const float* src = Qin + (size_t)n * DMODEL + h * DHEAD;
    float v0 = src[lane], v1 = src[lane + 32];
    float ss = v0 * v0 + v1 * v1;
    #pragma unroll
    for (int s = 16; s; s >>= 1) ss += __shfl_xor_sync(0xffffffffu, ss, s);
    float inv = 1.0f / fmaxf(sqrtf(ss), 1e-12f);
    float* dst = QN + ((size_t)h * Nq + n) * DHEAD;
    dst[lane]      = v0 * inv * qs[lane] * 8.0f;        // fold sim *SCALE into q
    dst[lane + 32] = v1 * inv * qs[lane + 32] * 8.0f;
}

// ---------------- KV prep: prepend null row, l2norm(k)*ks, layout [H][NK][64] ----------------
__global__ void prep_kv_kernel(const float* __restrict__ KVin, const float* __restrict__ nullp,
                               const float* __restrict__ ks, float* __restrict__ Ko,
                               float* __restrict__ Vo, int Nt) {
    int NK = Nt + 1;
    int gw = (blockIdx.x * blockDim.x + threadIdx.x) >> 5;
    int lane = threadIdx.x & 31;
    if (gw >= NHEAD * NK) return;
    int h = gw / NK, j = gw % NK;
    float k0, k1, v0, v1;
    if (j == 0) {
        k0 = nullp[h * DHEAD + lane];
        k1 = nullp[h * DHEAD + lane + 32];
        v0 = nullp[NHEAD * DHEAD + h * DHEAD + lane];
        v1 = nullp[NHEAD * DHEAD + h * DHEAD + lane + 32];
    } else {
        const float* src = KVin + (size_t)(j - 1) * (2 * DMODEL) + h * DHEAD;
        k0 = src[lane];          k1 = src[lane + 32];
        v0 = src[DMODEL + lane]; v1 = src[DMODEL + lane + 32];
    }
    float ss = k0 * k0 + k1 * k1;
    #pragma unroll
    for (int s = 16; s; s >>= 1) ss += __shfl_xor_sync(0xffffffffu, ss, s);
    float inv = 1.0f / fmaxf(sqrtf(ss), 1e-12f);
    size_t base = ((size_t)h * NK + j) * DHEAD;
    Ko[base + lane]      = k0 * inv * ks[lane];
    Ko[base + lane + 32] = k1 * inv * ks[lane + 32];
    Vo[base + lane]      = v0;
    Vo[base + lane + 32] = v1;
}

// ---------------- fused flash attention: QB=128 rows, KB=64 keys, online softmax ----------------
// dynamic smem: Qs[128*64] | KT[64*64] (K transposed, reused for V row-major) | Ps[128*64]
__global__ __launch_bounds__(256, 2)
void flash_kernel(const float* __restrict__ Q, const float* __restrict__ K,
                  const float* __restrict__ V, float* __restrict__ O,
                  int Nq, int NK) {
    extern __shared__ float sm[];
    float* Qs = sm;            // 8192
    float* KT = sm + 8192;     // 4096 (K^T then V)
    float* Ps = sm + 12288;    // 8192
    int h  = blockIdx.y;
    int qb = blockIdx.x * 128;
    int tid = threadIdx.x;
    int tx = tid & 15, ty = tid >> 4;
    int r0 = ty * 8, c0 = tx * 4;

    const float* Qg = Q + ((size_t)h * Nq + qb) * DHEAD;
    for (int i = tid * 4; i < 8192; i += 1024)
        *(float4*)&Qs[i] = *(const float4*)&Qg[i];

    float o[8][4];
    float mrow[8], lrow[8];
    #pragma unroll
    for (int i = 0; i < 8; i++) {
        mrow[i] = -1e30f; lrow[i] = 0.f;
        o[i][0] = o[i][1] = o[i][2] = o[i][3] = 0.f;
    }

    int ntiles = (NK + 63) >> 6;
    int kj = tid & 63, kd = (tid >> 6) << 4;   // transpose-load mapping

    for (int t = 0; t < ntiles; t++) {
        int kb = t << 6;
        __syncthreads();  // prev-iter readers of KT/Ps done
        {   // load K tile transposed: KT[d][j]
            bool valid = (kb + kj) < NK;
            const float* Kg = K + ((size_t)h * NK + kb + kj) * DHEAD;
            #pragma unroll
            for (int r = 0; r < 4; r++) {
                int d0 = kd + r * 4;
                float4 g = valid ? *(const float4*)&Kg[d0] : make_float4(0, 0, 0, 0);
                KT[(d0 + 0) * 64 + kj] = g.x;
                KT[(d0 + 1) * 64 + kj] = g.y;
                KT[(d0 + 2) * 64 + kj] = g.z;
                KT[(d0 + 3) * 64 + kj] = g.w;
            }
        }
        __syncthreads();

        // S = Q K^T  (per-thread 8x4 tile)
        float acc[8][4];
        #pragma unroll
        for (int i = 0; i < 8; i++) acc[i][0] = acc[i][1] = acc[i][2] = acc[i][3] = 0.f;
        #pragma unroll
        for (int d = 0; d < 64; d += 4) {
            float4 k4[4];
            #pragma unroll
            for (int j = 0; j < 4; j++) k4[j] = *(float4*)&KT[(d + j) * 64 + c0];
            #pragma unroll
            for (int i = 0; i < 8; i++) {
                float4 q4 = *(float4*)&Qs[(r0 + i) * 64 + d];
                acc[i][0] += q4.x * k4[0].x + q4.y * k4[1].x + q4.z * k4[2].x + q4.w * k4[3].x;
                acc[i][1] += q4.x * k4[0].y + q4.y * k4[1].y + q4.z * k4[2].y + q4.w * k4[3].y;
                acc[i][2] += q4.x * k4[0].z + q4.y * k4[1].z + q4.z * k4[2].z + q4.w * k4[3].z;
                acc[i][3] += q4.x * k4[0].w + q4.y * k4[1].w + q4.z * k4[2].w + q4.w * k4[3].w;
            }
        }
        // mask OOB keys
        if (kb + 64 > NK) {
            #pragma unroll
            for (int j = 0; j < 4; j++)
                if (kb + c0 + j >= NK)
                    #pragma unroll
                    for (int i = 0; i < 8; i++) acc[i][j] = -1e30f;
        }
        // online softmax
        float tmax[8];
        #pragma unroll
        for (int i = 0; i < 8; i++)
            tmax[i] = fmaxf(fmaxf(acc[i][0], acc[i][1]), fmaxf(acc[i][2], acc[i][3]));
        #pragma unroll
        for (int s = 1; s < 16; s <<= 1)
            #pragma unroll
            for (int i = 0; i < 8; i++)
                tmax[i] = fmaxf(tmax[i], __shfl_xor_sync(0xffffffffu, tmax[i], s, 32));
        float corr[8];
        #pragma unroll
        for (int i = 0; i < 8; i++) {
            float mnew = fmaxf(mrow[i], tmax[i]);
            corr[i] = expf(mrow[i] - mnew);
            mrow[i] = mnew;
        }
        float rsum[8];
        #pragma unroll
        for (int i = 0; i < 8; i++) {
            float s = 0.f;
            #pragma unroll
            for (int j = 0; j < 4; j++) {
                float p = expf(acc[i][j] - mrow[i]);
                acc[i][j] = p; s += p;
            }
            rsum[i] = s;
        }
        #pragma unroll
        for (int s = 1; s < 16; s <<= 1)
            #pragma unroll
            for (int i = 0; i < 8; i++)
                rsum[i] += __shfl_xor_sync(0xffffffffu, rsum[i], s, 32);
        #pragma unroll
        for (int i = 0; i < 8; i++) {
            lrow[i] = lrow[i] * corr[i] + rsum[i];
            o[i][0] *= corr[i]; o[i][1] *= corr[i]; o[i][2] *= corr[i]; o[i][3] *= corr[i];
            *(float4*)&Ps[(r0 + i) * 64 + c0] = make_float4(acc[i][0], acc[i][1], acc[i][2], acc[i][3]);
        }
        __syncthreads();  // Ps written; KT reads (S stage) done
        // load V tile row-major into KT
        for (int i = tid * 4; i < 4096; i += 1024) {
            int j = i >> 6;
            *(float4*)&KT[i] = (kb + j < NK)
                ? *(const float4*)&V[((size_t)h * NK + kb + j) * DHEAD + (i & 63)]
                : make_float4(0, 0, 0, 0);
        }
        __syncthreads();
        // O += P @ V
        #pragma unroll
        for (int jk = 0; jk < 64; jk += 4) {
            float4 v4[4];
            #pragma unroll
            for (int jj = 0; jj < 4; jj++) v4[jj] = *(float4*)&KT[(jk + jj) * 64 + c0];
            #pragma unroll
            for (int i = 0; i < 8; i++) {
                float4 p4 = *(float4*)&Ps[(r0 + i) * 64 + jk];
                o[i][0] += p4.x * v4[0].x + p4.y * v4[1].x + p4.z * v4[2].x + p4.w * v4[3].x;
                o[i][1] += p4.x * v4[0].y + p4.y * v4[1].y + p4.z * v4[2].y + p4.w * v4[3].y;
                o[i][2] += p4.x * v4[0].z + p4.y * v4[1].z + p4.z * v4[2].z + p4.w * v4[3].z;
                o[i][3] += p4.x * v4[0].w + p4.y * v4[1].w + p4.z * v4[2].w + p4.w * v4[3].w;
            }
        }
    }
    // epilogue: O[n][h*64 + c] = o / l   (layout (n, h*dh))
    #pragma unroll
    for (int i = 0; i < 8; i++) {
        float inv = 1.f / lrow[i];
        int n = qb + r0 + i;
        float4 w = make_float4(o[i][0] * inv, o[i][1] * inv, o[i][2] * inv, o[i][3] * inv);
        *(float4*)&O[(size_t)n * DMODEL + h * DHEAD + c0] = w;
    }
}

// ---------------- GEMM: C[M,N] = A[M,K] @ B[K,N] (+C), 128x128x8 tiles, f32x2 FMA ----------------
// B loads vectorized (all N used are divisible by 4; column origins 4-aligned).
__global__ __launch_bounds__(256, 2)
void gemm_kernel(const float* __restrict__ A, const float* __restrict__ B,
                 float* __restrict__ C, int M, int N, int K, int addC) {
    __shared__ float As[8][128];   // transposed A tile
    __shared__ float Bs[8][128];
    int tid = threadIdx.x;
    int tx = tid & 15, ty = tid >> 4;
    int row0 = blockIdx.y * 128 + ty * 8;
    int col0 = blockIdx.x * 128 + tx * 8;
    unsigned long long acc[8][4];
    #pragma unroll
    for (int i = 0; i < 8; i++)
        #pragma unroll
        for (int j = 0; j < 4; j++) acc[i][j] = 0ull;

    int aRow = tid >> 1, aCol = (tid & 1) * 4;
    int bRow = tid >> 5, bCol = (tid & 31) * 4;
    int gra = blockIdx.y * 128 + aRow;
    int gcb = blockIdx.x * 128 + bCol;

    for (int k0 = 0; k0 < K; k0 += 8) {
        #pragma unroll
        for (int i = 0; i < 4; i++) {
            int gc = k0 + aCol + i;
            As[aCol + i][aRow] = (gra < M && gc < K) ? A[(size_t)gra * K + gc] : 0.f;
        }
        {
            int gk = k0 + bRow;
            float4 bv = (gk < K && gcb < N) ? *(const float4*)&B[(size_t)gk * N + gcb]
                                            : make_float4(0, 0, 0, 0);
            *(float4*)&Bs[bRow][bCol] = bv;
        }
        __syncthreads();
        #pragma unroll
        for (int k = 0; k < 8; k++) {
            float4 a0 = *(float4*)&As[k][ty * 8];
            float4 a1 = *(float4*)&As[k][ty * 8 + 4];
            ulonglong2 b0 = *(ulonglong2*)&Bs[k][tx * 8];
            ulonglong2 b1 = *(ulonglong2*)&Bs[k][tx * 8 + 4];
            float av[8] = {a0.x, a0.y, a0.z, a0.w, a1.x, a1.y, a1.z, a1.w};
            #pragma unroll
            for (int i = 0; i < 8; i++) {
                unsigned long long a2 = bcast2(av[i]);
                fma2(acc[i][0], a2, b0.x);
                fma2(acc[i][1], a2, b0.y);
                fma2(acc[i][2], a2, b1.x);
                fma2(acc[i][3], a2, b1.y);
            }
        }
        __syncthreads();
    }
    #pragma unroll
    for (int i = 0; i < 8; i++) {
        int r = row0 + i;
        if (r >= M) continue;
        #pragma unroll
        for (int j = 0; j < 4; j++) {
            float2 v = unpack2(acc[i][j]);
            int c = col0 + 2 * j;
            if (c < N)     { float ov = v.x; if (addC) ov += C[(size_t)r * N + c];     C[(size_t)r * N + c]     = ov; }
            if (c + 1 < N) { float ov = v.y; if (addC) ov += C[(size_t)r * N + c + 1]; C[(size_t)r * N + c + 1] = ov; }
        }
    }
}

// ---------------- host orchestration ----------------
extern "C" void kernel_launch(void* const* d_in, const int* in_sizes, int n_in,
                              void* d_out, int out_size) {
    (void)in_sizes; (void)n_in; (void)out_size;
    const int*   x_ids    = (const int*)d_in[0];
    const int*   cond_ids = (const int*)d_in[1];
    const float* token_emb = (const float*)d_in[2];
    const float* pos_emb   = (const float*)d_in[3];
    const float* cte       = (const float*)d_in[4];
    const float* cpe       = (const float*)d_in[5];
    const float* sa_g    = (const float*)d_in[6];
    const float* sa_wq   = (const float*)d_in[7];
    const float* sa_wkv  = (const float*)d_in[8];
    const float* sa_null = (const float*)d_in[9];
    const float* sa_qs   = (const float*)d_in[10];
    const float* sa_ks   = (const float*)d_in[11];
    const float* sa_wo   = (const float*)d_in[12];
    const float* ca_g    = (const float*)d_in[13];
    const float* ca_wq   = (const float*)d_in[14];
    const float* ca_wkv  = (const float*)d_in[15];
    const float* ca_null = (const float*)d_in[16];
    const float* ca_qs   = (const float*)d_in[17];
    const float* ca_ks   = (const float*)d_in[18];
    const float* ca_wo   = (const float*)d_in[19];
    const float* ff_g1   = (const float*)d_in[20];
    const float* ff_w1   = (const float*)d_in[21];
    const float* ff_g2   = (const float*)d_in[22];
    const float* ff_w2   = (const float*)d_in[23];
    const float* final_g  = (const float*)d_in[24];
    const float* w_logits = (const float*)d_in[25];
    float* out = (float*)d_out;

    float *H, *CTX, *XN, *Q, *KV, *QN, *K, *V, *O, *HH, *GN;
    cudaGetSymbolAddress((void**)&H,   g_H);
    cudaGetSymbolAddress((void**)&CTX, g_CTX);
    cudaGetSymbolAddress((void**)&XN,  g_XN);
    cudaGetSymbolAddress((void**)&Q,   g_Q);
    cudaGetSymbolAddress((void**)&KV,  g_KV);
    cudaGetSymbolAddress((void**)&QN,  g_QN);
    cudaGetSymbolAddress((void**)&K,   g_K);
    cudaGetSymbolAddress((void**)&V,   g_V);
    cudaGetSymbolAddress((void**)&O,   g_O);
    cudaGetSymbolAddress((void**)&HH,  g_HH);
    cudaGetSymbolAddress((void**)&GN,  g_GN);

    const int FLASH_SMEM = 20480 * 4;  // 80KB dynamic
    cudaFuncSetAttribute(flash_kernel, cudaFuncAttributeMaxDynamicSharedMemorySize, FLASH_SMEM);

    embed_img_kernel<<<(NTOK * DMODEL) / 256, 256>>>(x_ids, token_emb, pos_emb, H);
    embed_ctx_kernel<<<(NCTX * DMODEL) / 256, 256>>>(cond_ids, cte, cpe, CTX);

    for (int l = 0; l < NLAYER; l++) {
        // ------- self attention -------
        ln_kernel<<<NTOK, 256>>>(H, sa_g + (size_t)l * DMODEL, XN, DMODEL);
        gemm_kernel<<<dim3(8, 12), 256>>>(XN, sa_wq + (size_t)l * DMODEL * DMODEL, Q, NTOK, DMODEL, DMODEL, 0);
        gemm_kernel<<<dim3(16, 12), 256>>>(XN, sa_wkv + (size_t)l * DMODEL * 2 * DMODEL, KV, NTOK, 2 * DMODEL, DMODEL, 0);
        prep_q_kernel<<<(NHEAD * NTOK + 7) / 8, 256>>>(Q, sa_qs + l * DHEAD, QN, NTOK);
        prep_kv_kernel<<<(NHEAD * (NTOK + 1) + 7) / 8, 256>>>(KV, sa_null + (size_t)l * 2 * NHEAD * DHEAD,
                                                              sa_ks + l * DHEAD, K, V, NTOK);
        flash_kernel<<<dim3(NTOK / 128, NHEAD), 256, FLASH_SMEM>>>(QN, K, V, O, NTOK, NTOK + 1);
        gemm_kernel<<<dim3(8, 12), 256>>>(O, sa_wo + (size_t)l * DMODEL * DMODEL, H, NTOK, DMODEL, DMODEL, 1);

        // ------- cross attention -------
        ln_kernel<<<NTOK, 256>>>(H, ca_g + (size_t)l * DMODEL, XN, DMODEL);
        gemm_kernel<<<dim3(8, 12), 256>>>(XN, ca_wq + (size_t)l * DMODEL * DMODEL, Q, NTOK, DMODEL, DMODEL, 0);
        gemm_kernel<<<dim3(16, 4), 256>>>(CTX, ca_wkv + (size_t)l * DMODEL * 2 * DMODEL, KV, NCTX, 2 * DMODEL, DMODEL, 0);
        prep_q_kernel<<<(NHEAD * NTOK + 7) / 8, 256>>>(Q, ca_qs + l * DHEAD, QN, NTOK);
        prep_kv_kernel<<<(NHEAD * (NCTX + 1) + 7) / 8, 256>>>(KV, ca_null + (size_t)l * 2 * NHEAD * DHEAD,
                                                              ca_ks + l * DHEAD, K, V, NCTX);
        flash_kernel<<<dim3(NTOK / 128, NHEAD), 256, FLASH_SMEM>>>(QN, K, V, O, NTOK, NCTX + 1);
        gemm_kernel<<<dim3(8, 12), 256>>>(O, ca_wo + (size_t)l * DMODEL * DMODEL, H, NTOK, DMODEL, DMODEL, 1);

        // ------- GEGLU feedforward -------
        ln_kernel<<<NTOK, 256>>>(H, ff_g1 + (size_t)l * DMODEL, XN, DMODEL);
        gemm_kernel<<<dim3((FF2 + 127) / 128, 12), 256>>>(XN, ff_w1 + (size_t)l * DMODEL * FF2, HH, NTOK, FF2, DMODEL, 0);
        geglu_ln_kernel<<<NTOK, 256>>>(HH, ff_g2 + (size_t)l * FFI, GN);
        gemm_kernel<<<dim3(8, 12), 256>>>(GN, ff_w2 + (size_t)l * FFI * DMODEL, H, NTOK, DMODEL, FFI, 1);
    }

    // ------- final norm + logits -------
    ln_kernel<<<NTOK, 256>>>(H, final_g, XN, DMODEL);
    gemm_kernel<<<dim3(VOCAB / 128, 12), 256>>>(XN, w_logits, out, NTOK, VOCAB, DMODEL, 0);
}

// round 5
// speedup vs baseline: 1.8106x; 1.8106x over previous
#include <cuda_runtime.h>
#include <cuda_bf16.h>
#include <math.h>
#include <stdint.h>

// ---------------- model dims ----------------
#define NLAYER 4
#define DMODEL 1024
#define NHEAD  16
#define DHEAD  64
#define NTOK   1536
#define NCTX   512
#define VOCAB  8192
#define FFI    2730          // GEGLU inner
#define FF2    5460          // 2*FFI

// ---------------- scratch (device globals; no allocation allowed) ----------------
__device__ float g_H  [NTOK * DMODEL];
__device__ float g_CTX[NCTX * DMODEL];
__device__ float g_XN [NTOK * DMODEL];
__device__ float g_Q  [NTOK * DMODEL];
__device__ float g_KV [NTOK * 2 * DMODEL];
__device__ float g_QN [NHEAD * NTOK * DHEAD];
__device__ float g_K  [NHEAD * (NTOK + 1) * DHEAD];
__device__ float g_V  [NHEAD * (NTOK + 1) * DHEAD];
__device__ float g_O  [NTOK * DMODEL];
__device__ float g_HH [NTOK * FF2];
__device__ float g_GN [NTOK * FFI];

// ---------------- helpers ----------------
__device__ __forceinline__ uint32_t smem_u32(const void* p) {
    uint32_t a;
    asm("{ .reg .u64 t; cvta.to.shared.u64 t, %1; cvt.u32.u64 %0, t; }" : "=r"(a) : "l"(p));
    return a;
}
// split fp32 pair -> packed bf16x2 hi and lo (residual)
__device__ __forceinline__ void split2(float f0, float f1, uint32_t& hi, uint32_t& lo) {
    __nv_bfloat16 h0 = __float2bfloat16(f0), h1 = __float2bfloat16(f1);
    float r0 = f0 - __bfloat162float(h0), r1 = f1 - __bfloat162float(h1);
    __nv_bfloat16 l0 = __float2bfloat16(r0), l1 = __float2bfloat16(r1);
    hi = (uint32_t)__bfloat16_as_ushort(h0) | ((uint32_t)__bfloat16_as_ushort(h1) << 16);
    lo = (uint32_t)__bfloat16_as_ushort(l0) | ((uint32_t)__bfloat16_as_ushort(l1) << 16);
}
__device__ __forceinline__ void ldsm4(uint32_t* r, uint32_t addr) {
    asm volatile("ldmatrix.sync.aligned.m8n8.x4.shared.b16 {%0,%1,%2,%3}, [%4];"
                 : "=r"(r[0]), "=r"(r[1]), "=r"(r[2]), "=r"(r[3]) : "r"(addr));
}
__device__ __forceinline__ void mma16816(float* c, const uint32_t* a, uint32_t b0, uint32_t b1) {
    asm volatile(
        "mma.sync.aligned.m16n8k16.row.col.f32.bf16.bf16.f32 "
        "{%0,%1,%2,%3}, {%4,%5,%6,%7}, {%8,%9}, {%0,%1,%2,%3};"
        : "+f"(c[0]), "+f"(c[1]), "+f"(c[2]), "+f"(c[3])
        : "r"(a[0]), "r"(a[1]), "r"(a[2]), "r"(a[3]), "r"(b0), "r"(b1));
}

// ---------------- tensor-core GEMM via mma.sync: C[M,N] = A[M,K] @ B[K,N] (+C) ----
// 128x128 CTA tile, BK=64, 8 warps (warp tile 32x64), SW128 swizzle, bf16 hi/lo split.
// smem: Ahi[128][64] Alo Bhi(B^T [n][k]) Blo, bf16 -> 64KB dynamic.
__global__ __launch_bounds__(256, 1)
void gemm_mma_kernel(const float* __restrict__ A, const float* __restrict__ B,
                     float* __restrict__ C, int M, int N, int K, int addC) {
    extern __shared__ char sm_raw[];
    __nv_bfloat16* Ah = (__nv_bfloat16*)sm_raw;          // 128*64
    __nv_bfloat16* Al = Ah + 128 * 64;
    __nv_bfloat16* Bh = Al + 128 * 64;                   // B^T [128 n][64 k]
    __nv_bfloat16* Bl = Bh + 128 * 64;
    uint32_t aH = smem_u32(Ah), aL = smem_u32(Al), bH = smem_u32(Bh), bL = smem_u32(Bl);

    int tid = threadIdx.x;
    int warp = tid >> 5, lane = tid & 31;
    int wm = (warp >> 1) * 32, wn = (warp & 1) * 64;
    int m0 = blockIdx.y * 128, n0 = blockIdx.x * 128;

    float acc[2][8][4];
    #pragma unroll
    for (int mi = 0; mi < 2; mi++)
        #pragma unroll
        for (int ni = 0; ni < 8; ni++)
            acc[mi][ni][0] = acc[mi][ni][1] = acc[mi][ni][2] = acc[mi][ni][3] = 0.f;

    int ktiles = (K + 63) >> 6;
    for (int kt = 0; kt < ktiles; kt++) {
        int k0 = kt << 6;
        __syncthreads();   // previous iteration's mma readers done

        // ---- stage A [128 rows][8 chunks of 8 k] ----
        #pragma unroll
        for (int i = 0; i < 4; i++) {
            int cid = tid + i * 256;          // 0..1023
            int row = cid >> 3, c = cid & 7;
            int gm = m0 + row, gk = k0 + c * 8;
            const float* ap = A + (size_t)gm * K + gk;
            float f[8];
            #pragma unroll
            for (int j = 0; j < 4; j++) {
                float2 v = (gk + 2 * j + 1 < K) ? *(const float2*)(ap + 2 * j)
                                                : make_float2(0.f, 0.f);
                f[2 * j] = v.x; f[2 * j + 1] = v.y;
            }
            uint32_t hi[4], lo[4];
            #pragma unroll
            for (int j = 0; j < 4; j++) split2(f[2 * j], f[2 * j + 1], hi[j], lo[j]);
            uint32_t off = (uint32_t)row * 128 + (uint32_t)((c ^ (row & 7)) << 4);
            *(uint4*)((char*)Ah + off) = make_uint4(hi[0], hi[1], hi[2], hi[3]);
            *(uint4*)((char*)Al + off) = make_uint4(lo[0], lo[1], lo[2], lo[3]);
        }
        // ---- stage B^T [128 n][8 chunks of 8 k] (transpose; coalesced across n) ----
        #pragma unroll
        for (int i = 0; i < 4; i++) {
            int cid = tid + i * 256;
            int nr = cid & 127, kc = cid >> 7;
            int gn = n0 + nr;
            float f[8];
            #pragma unroll
            for (int j = 0; j < 8; j++) {
                int gk = k0 + kc * 8 + j;
                f[j] = (gk < K && gn < N) ? B[(size_t)gk * N + gn] : 0.f;
            }
            uint32_t hi[4], lo[4];
            #pragma unroll
            for (int j = 0; j < 4; j++) split2(f[2 * j], f[2 * j + 1], hi[j], lo[j]);
            uint32_t off = (uint32_t)nr * 128 + (uint32_t)((kc ^ (nr & 7)) << 4);
            *(uint4*)((char*)Bh + off) = make_uint4(hi[0], hi[1], hi[2], hi[3]);
            *(uint4*)((char*)Bl + off) = make_uint4(lo[0], lo[1], lo[2], lo[3]);
        }
        __syncthreads();

        // ---- mma over 4 k16 steps ----
        #pragma unroll
        for (int ks = 0; ks < 4; ks++) {
            uint32_t ah[2][4], al[2][4];
            #pragma unroll
            for (int mi = 0; mi < 2; mi++) {
                int row = wm + mi * 16 + (lane & 15);
                int c = ks * 2 + (lane >> 4);
                uint32_t off = (uint32_t)row * 128 + (uint32_t)((c ^ (row & 7)) << 4);
                ldsm4(ah[mi], aH + off);
                ldsm4(al[mi], aL + off);
            }
            #pragma unroll
            for (int np = 0; np < 4; np++) {
                uint32_t bh[4], bl[4];
                int row = wn + np * 16 + (lane & 15);
                int c = ks * 2 + (lane >> 4);
                uint32_t off = (uint32_t)row * 128 + (uint32_t)((c ^ (row & 7)) << 4);
                ldsm4(bh, bH + off);
                ldsm4(bl, bL + off);
                #pragma unroll
                for (int mi = 0; mi < 2; mi++) {
                    mma16816(acc[mi][2 * np],     ah[mi], bh[0], bh[2]);
                    mma16816(acc[mi][2 * np],     al[mi], bh[0], bh[2]);
                    mma16816(acc[mi][2 * np],     ah[mi], bl[0], bl[2]);
                    mma16816(acc[mi][2 * np + 1], ah[mi], bh[1], bh[3]);
                    mma16816(acc[mi][2 * np + 1], al[mi], bh[1], bh[3]);
                    mma16816(acc[mi][2 * np + 1], ah[mi], bl[1], bl[3]);
                }
            }
        }
    }

    // ---- epilogue ----
    int gid = lane >> 2, tig = lane & 3;
    #pragma unroll
    for (int mi = 0; mi < 2; mi++) {
        #pragma unroll
        for (int ni = 0; ni < 8; ni++) {
            int row = m0 + wm + mi * 16 + gid;
            int col = n0 + wn + ni * 8 + tig * 2;
            if (col + 1 < N && row < M) {
                float* cp = &C[(size_t)row * N + col];
                float2 v = make_float2(acc[mi][ni][0], acc[mi][ni][1]);
                if (addC) { float2 o = *(float2*)cp; v.x += o.x; v.y += o.y; }
                *(float2*)cp = v;
                float* cp8 = cp + 8 * (size_t)N;
                float2 w = make_float2(acc[mi][ni][2], acc[mi][ni][3]);
                if (addC) { float2 o = *(float2*)cp8; w.x += o.x; w.y += o.y; }
                *(float2*)cp8 = w;
            }
        }
    }
}

// ---------------- embeddings ----------------
__global__ void embed_img_kernel(const int* __restrict__ ids, const float* __restrict__ te,
                                 const float* __restrict__ pe, float* __restrict__ out) {
    int i = blockIdx.x * blockDim.x + threadIdx.x;
    if (i >= NTOK * DMODEL) return;
    int n = i >> 10, d = i & 1023;
    out[i] = te[(size_t)ids[n] * DMODEL + d] + pe[i];
}
__global__ void embed_ctx_kernel(const int* __restrict__ ids, const float* __restrict__ te,
                                 const float* __restrict__ pe, float* __restrict__ out) {
    int i = blockIdx.x * blockDim.x + threadIdx.x;
    if (i >= NCTX * DMODEL) return;
    int n = i >> 10, d = i & 1023;
    out[i] = te[(size_t)ids[n] * DMODEL + d] + pe[i];
}

// ---------------- LayerNorm ----------------
__global__ void ln_kernel(const float* __restrict__ X, const float* __restrict__ g,
                          float* __restrict__ Y, int C) {
    int row = blockIdx.x;
    const float* x = X + (size_t)row * C;
    float* y = Y + (size_t)row * C;
    int tid = threadIdx.x;
    float s1 = 0.f, s2 = 0.f;
    for (int c = tid; c < C; c += 256) { float v = x[c]; s1 += v; s2 += v * v; }
    __shared__ float red[512];
    red[tid] = s1; red[256 + tid] = s2;
    __syncthreads();
    for (int s = 128; s > 0; s >>= 1) {
        if (tid < s) { red[tid] += red[tid + s]; red[256 + tid] += red[256 + tid + s]; }
        __syncthreads();
    }
    float mean = red[0] / C;
    float var  = red[256] / C - mean * mean;
    float inv  = rsqrtf(var + 1e-5f);
    for (int c = tid; c < C; c += 256) y[c] = (x[c] - mean) * inv * g[c];
}

// ---------------- fused GEGLU + LayerNorm ----------------
__global__ void geglu_ln_kernel(const float* __restrict__ HH, const float* __restrict__ g2,
                                float* __restrict__ Y) {
    int row = blockIdx.x;
    const float* h = HH + (size_t)row * FF2;
    float* y = Y + (size_t)row * FFI;
    int tid = threadIdx.x;
    __shared__ float buf[FFI];
    __shared__ float red[512];
    float s1 = 0.f, s2 = 0.f;
    for (int c = tid; c < FFI; c += 256) {
        float a = h[c], gate = h[FFI + c];
        float v = gate * (0.5f * a * (1.0f + erff(a * 0.70710678118654752f)));
        buf[c] = v; s1 += v; s2 += v * v;
    }
    red[tid] = s1; red[256 + tid] = s2;
    __syncthreads();
    for (int s = 128; s > 0; s >>= 1) {
        if (tid < s) { red[tid] += red[tid + s]; red[256 + tid] += red[256 + tid + s]; }
        __syncthreads();
    }
    float mean = red[0] / FFI;
    float var  = red[256] / FFI - mean * mean;
    float inv  = rsqrtf(var + 1e-5f);
    for (int c = tid; c < FFI; c += 256) y[c] = (buf[c] - mean) * inv * g2[c];
}

// ---------------- Q prep ----------------
__global__ void prep_q_kernel(const float* __restrict__ Qin, const float* __restrict__ qs,
                              float* __restrict__ QN, int Nq) {
    int gw = (blockIdx.x * blockDim.x + threadIdx.x) >> 5;
    int lane = threadIdx.x & 31;
    if (gw >= NHEAD * Nq) return;
    int h = gw / Nq, n = gw % Nq;
    const float* src = Qin + (size_t)n * DMODEL + h * DHEAD;
    float v0 = src[lane], v1 = src[lane + 32];
    float ss = v0 * v0 + v1 * v1;
    #pragma unroll
    for (int s = 16; s; s >>= 1) ss += __shfl_xor_sync(0xffffffffu, ss, s);
    float inv = 1.0f / fmaxf(sqrtf(ss), 1e-12f);
    float* dst = QN + ((size_t)h * Nq + n) * DHEAD;
    dst[lane]      = v0 * inv * qs[lane] * 8.0f;
    dst[lane + 32] = v1 * inv * qs[lane + 32] * 8.0f;
}

// ---------------- KV prep ----------------
__global__ void prep_kv_kernel(const float* __restrict__ KVin, const float* __restrict__ nullp,
                               const float* __restrict__ ks, float* __restrict__ Ko,
                               float* __restrict__ Vo, int Nt) {
    int NK = Nt + 1;
    int gw = (blockIdx.x * blockDim.x + threadIdx.x) >> 5;
    int lane = threadIdx.x & 31;
    if (gw >= NHEAD * NK) return;
    int h = gw / NK, j = gw % NK;
    float k0, k1, v0, v1;
    if (j == 0) {
        k0 = nullp[h * DHEAD + lane];
        k1 = nullp[h * DHEAD + lane + 32];
        v0 = nullp[NHEAD * DHEAD + h * DHEAD + lane];
        v1 = nullp[NHEAD * DHEAD + h * DHEAD + lane + 32];
    } else {
        const float* src = KVin + (size_t)(j - 1) * (2 * DMODEL) + h * DHEAD;
        k0 = src[lane];          k1 = src[lane + 32];
        v0 = src[DMODEL + lane]; v1 = src[DMODEL + lane + 32];
    }
    float ss = k0 * k0 + k1 * k1;
    #pragma unroll
    for (int s = 16; s; s >>= 1) ss += __shfl_xor_sync(0xffffffffu, ss, s);
    float inv = 1.0f / fmaxf(sqrtf(ss), 1e-12f);
    size_t base = ((size_t)h * NK + j) * DHEAD;
    Ko[base + lane]      = k0 * inv * ks[lane];
    Ko[base + lane + 32] = k1 * inv * ks[lane + 32];
    Vo[base + lane]      = v0;
    Vo[base + lane + 32] = v1;
}

// ---------------- fused flash attention (scalar, proven) ----------------
__global__ __launch_bounds__(256, 2)
void flash_kernel(const float* __restrict__ Q, const float* __restrict__ K,
                  const float* __restrict__ V, float* __restrict__ O,
                  int Nq, int NK) {
    extern __shared__ float sm[];
    float* Qs = sm;
    float* KT = sm + 8192;
    float* Ps = sm + 12288;
    int h  = blockIdx.y;
    int qb = blockIdx.x * 128;
    int tid = threadIdx.x;
    int tx = tid & 15, ty = tid >> 4;
    int r0 = ty * 8, c0 = tx * 4;

    const float* Qg = Q + ((size_t)h * Nq + qb) * DHEAD;
    for (int i = tid * 4; i < 8192; i += 1024)
        *(float4*)&Qs[i] = *(const float4*)&Qg[i];

    float o[8][4];
    float mrow[8], lrow[8];
    #pragma unroll
    for (int i = 0; i < 8; i++) {
        mrow[i] = -1e30f; lrow[i] = 0.f;
        o[i][0] = o[i][1] = o[i][2] = o[i][3] = 0.f;
    }

    int ntiles = (NK + 63) >> 6;
    int kj = tid & 63, kd = (tid >> 6) << 4;

    for (int t = 0; t < ntiles; t++) {
        int kb = t << 6;
        __syncthreads();
        {
            bool valid = (kb + kj) < NK;
            const float* Kg = K + ((size_t)h * NK + kb + kj) * DHEAD;
            #pragma unroll
            for (int r = 0; r < 4; r++) {
                int d0 = kd + r * 4;
                float4 g = valid ? *(const float4*)&Kg[d0] : make_float4(0, 0, 0, 0);
                KT[(d0 + 0) * 64 + kj] = g.x;
                KT[(d0 + 1) * 64 + kj] = g.y;
                KT[(d0 + 2) * 64 + kj] = g.z;
                KT[(d0 + 3) * 64 + kj] = g.w;
            }
        }
        __syncthreads();

        float acc[8][4];
        #pragma unroll
        for (int i = 0; i < 8; i++) acc[i][0] = acc[i][1] = acc[i][2] = acc[i][3] = 0.f;
        #pragma unroll
        for (int d = 0; d < 64; d += 4) {
            float4 k4[4];
            #pragma unroll
            for (int j = 0; j < 4; j++) k4[j] = *(float4*)&KT[(d + j) * 64 + c0];
            #pragma unroll
            for (int i = 0; i < 8; i++) {
                float4 q4 = *(float4*)&Qs[(r0 + i) * 64 + d];
                acc[i][0] += q4.x * k4[0].x + q4.y * k4[1].x + q4.z * k4[2].x + q4.w * k4[3].x;
                acc[i][1] += q4.x * k4[0].y + q4.y * k4[1].y + q4.z * k4[2].y + q4.w * k4[3].y;
                acc[i][2] += q4.x * k4[0].z + q4.y * k4[1].z + q4.z * k4[2].z + q4.w * k4[3].z;
                acc[i][3] += q4.x * k4[0].w + q4.y * k4[1].w + q4.z * k4[2].w + q4.w * k4[3].w;
            }
        }
        if (kb + 64 > NK) {
            #pragma unroll
            for (int j = 0; j < 4; j++)
                if (kb + c0 + j >= NK)
                    #pragma unroll
                    for (int i = 0; i < 8; i++) acc[i][j] = -1e30f;
        }
        float tmax[8];
        #pragma unroll
        for (int i = 0; i < 8; i++)
            tmax[i] = fmaxf(fmaxf(acc[i][0], acc[i][1]), fmaxf(acc[i][2], acc[i][3]));
        #pragma unroll
        for (int s = 1; s < 16; s <<= 1)
            #pragma unroll
            for (int i = 0; i < 8; i++)
                tmax[i] = fmaxf(tmax[i], __shfl_xor_sync(0xffffffffu, tmax[i], s, 32));
        float corr[8];
        #pragma unroll
        for (int i = 0; i < 8; i++) {
            float mnew = fmaxf(mrow[i], tmax[i]);
            corr[i] = expf(mrow[i] - mnew);
            mrow[i] = mnew;
        }
        float rsum[8];
        #pragma unroll
        for (int i = 0; i < 8; i++) {
            float s = 0.f;
            #pragma unroll
            for (int j = 0; j < 4; j++) {
                float p = expf(acc[i][j] - mrow[i]);
                acc[i][j] = p; s += p;
            }
            rsum[i] = s;
        }
        #pragma unroll
        for (int s = 1; s < 16; s <<= 1)
            #pragma unroll
            for (int i = 0; i < 8; i++)
                rsum[i] += __shfl_xor_sync(0xffffffffu, rsum[i], s, 32);
        #pragma unroll
        for (int i = 0; i < 8; i++) {
            lrow[i] = lrow[i] * corr[i] + rsum[i];
            o[i][0] *= corr[i]; o[i][1] *= corr[i]; o[i][2] *= corr[i]; o[i][3] *= corr[i];
            *(float4*)&Ps[(r0 + i) * 64 + c0] = make_float4(acc[i][0], acc[i][1], acc[i][2], acc[i][3]);
        }
        __syncthreads();
        for (int i = tid * 4; i < 4096; i += 1024) {
            int j = i >> 6;
            *(float4*)&KT[i] = (kb + j < NK)
                ? *(const float4*)&V[((size_t)h * NK + kb + j) * DHEAD + (i & 63)]
                : make_float4(0, 0, 0, 0);
        }
        __syncthreads();
        #pragma unroll
        for (int jk = 0; jk < 64; jk += 4) {
            float4 v4[4];
            #pragma unroll
            for (int jj = 0; jj < 4; jj++) v4[jj] = *(float4*)&KT[(jk + jj) * 64 + c0];
            #pragma unroll
            for (int i = 0; i < 8; i++) {
                float4 p4 = *(float4*)&Ps[(r0 + i) * 64 + jk];
                o[i][0] += p4.x * v4[0].x + p4.y * v4[1].x + p4.z * v4[2].x + p4.w * v4[3].x;
                o[i][1] += p4.x * v4[0].y + p4.y * v4[1].y + p4.z * v4[2].y + p4.w * v4[3].y;
                o[i][2] += p4.x * v4[0].z + p4.y * v4[1].z + p4.z * v4[2].z + p4.w * v4[3].z;
                o[i][3] += p4.x * v4[0].w + p4.y * v4[1].w + p4.z * v4[2].w + p4.w * v4[3].w;
            }
        }
    }
    #pragma unroll
    for (int i = 0; i < 8; i++) {
        float inv = 1.f / lrow[i];
        int n = qb + r0 + i;
        float4 w = make_float4(o[i][0] * inv, o[i][1] * inv, o[i][2] * inv, o[i][3] * inv);
        *(float4*)&O[(size_t)n * DMODEL + h * DHEAD + c0] = w;
    }
}

// ---------------- host orchestration ----------------
extern "C" void kernel_launch(void* const* d_in, const int* in_sizes, int n_in,
                              void* d_out, int out_size) {
    (void)in_sizes; (void)n_in; (void)out_size;
    const int*   x_ids    = (const int*)d_in[0];
    const int*   cond_ids = (const int*)d_in[1];
    const float* token_emb = (const float*)d_in[2];
    const float* pos_emb   = (const float*)d_in[3];
    const float* cte       = (const float*)d_in[4];
    const float* cpe       = (const float*)d_in[5];
    const float* sa_g    = (const float*)d_in[6];
    const float* sa_wq   = (const float*)d_in[7];
    const float* sa_wkv  = (const float*)d_in[8];
    const float* sa_null = (const float*)d_in[9];
    const float* sa_qs   = (const float*)d_in[10];
    const float* sa_ks   = (const float*)d_in[11];
    const float* sa_wo   = (const float*)d_in[12];
    const float* ca_g    = (const float*)d_in[13];
    const float* ca_wq   = (const float*)d_in[14];
    const float* ca_wkv  = (const float*)d_in[15];
    const float* ca_null = (const float*)d_in[16];
    const float* ca_qs   = (const float*)d_in[17];
    const float* ca_ks   = (const float*)d_in[18];
    const float* ca_wo   = (const float*)d_in[19];
    const float* ff_g1   = (const float*)d_in[20];
    const float* ff_w1   = (const float*)d_in[21];
    const float* ff_g2   = (const float*)d_in[22];
    const float* ff_w2   = (const float*)d_in[23];
    const float* final_g  = (const float*)d_in[24];
    const float* w_logits = (const float*)d_in[25];
    float* out = (float*)d_out;

    float *H, *CTX, *XN, *Q, *KV, *QN, *K, *V, *O, *HH, *GN;
    cudaGetSymbolAddress((void**)&H,   g_H);
    cudaGetSymbolAddress((void**)&CTX, g_CTX);
    cudaGetSymbolAddress((void**)&XN,  g_XN);
    cudaGetSymbolAddress((void**)&Q,   g_Q);
    cudaGetSymbolAddress((void**)&KV,  g_KV);
    cudaGetSymbolAddress((void**)&QN,  g_QN);
    cudaGetSymbolAddress((void**)&K,   g_K);
    cudaGetSymbolAddress((void**)&V,   g_V);
    cudaGetSymbolAddress((void**)&O,   g_O);
    cudaGetSymbolAddress((void**)&HH,  g_HH);
    cudaGetSymbolAddress((void**)&GN,  g_GN);

    const int FLASH_SMEM = 20480 * 4;   // 80KB dynamic
    const int GEMM_SMEM  = 65536;       // 64KB dynamic
    cudaFuncSetAttribute(flash_kernel, cudaFuncAttributeMaxDynamicSharedMemorySize, FLASH_SMEM);
    cudaFuncSetAttribute(gemm_mma_kernel, cudaFuncAttributeMaxDynamicSharedMemorySize, GEMM_SMEM);

    embed_img_kernel<<<(NTOK * DMODEL) / 256, 256>>>(x_ids, token_emb, pos_emb, H);
    embed_ctx_kernel<<<(NCTX * DMODEL) / 256, 256>>>(cond_ids, cte, cpe, CTX);

    for (int l = 0; l < NLAYER; l++) {
        // ------- self attention -------
        ln_kernel<<<NTOK, 256>>>(H, sa_g + (size_t)l * DMODEL, XN, DMODEL);
        gemm_mma_kernel<<<dim3(8, 12), 256, GEMM_SMEM>>>(XN, sa_wq + (size_t)l * DMODEL * DMODEL, Q, NTOK, DMODEL, DMODEL, 0);
        gemm_mma_kernel<<<dim3(16, 12), 256, GEMM_SMEM>>>(XN, sa_wkv + (size_t)l * DMODEL * 2 * DMODEL, KV, NTOK, 2 * DMODEL, DMODEL, 0);
        prep_q_kernel<<<(NHEAD * NTOK + 7) / 8, 256>>>(Q, sa_qs + l * DHEAD, QN, NTOK);
        prep_kv_kernel<<<(NHEAD * (NTOK + 1) + 7) / 8, 256>>>(KV, sa_null + (size_t)l * 2 * NHEAD * DHEAD,
                                                              sa_ks + l * DHEAD, K, V, NTOK);
        flash_kernel<<<dim3(NTOK / 128, NHEAD), 256, FLASH_SMEM>>>(QN, K, V, O, NTOK, NTOK + 1);
        gemm_mma_kernel<<<dim3(8, 12), 256, GEMM_SMEM>>>(O, sa_wo + (size_t)l * DMODEL * DMODEL, H, NTOK, DMODEL, DMODEL, 1);

        // ------- cross attention -------
        ln_kernel<<<NTOK, 256>>>(H, ca_g + (size_t)l * DMODEL, XN, DMODEL);
        gemm_mma_kernel<<<dim3(8, 12), 256, GEMM_SMEM>>>(XN, ca_wq + (size_t)l * DMODEL * DMODEL, Q, NTOK, DMODEL, DMODEL, 0);
        gemm_mma_kernel<<<dim3(16, 4), 256, GEMM_SMEM>>>(CTX, ca_wkv + (size_t)l * DMODEL * 2 * DMODEL, KV, NCTX, 2 * DMODEL, DMODEL, 0);
        prep_q_kernel<<<(NHEAD * NTOK + 7) / 8, 256>>>(Q, ca_qs + l * DHEAD, QN, NTOK);
        prep_kv_kernel<<<(NHEAD * (NCTX + 1) + 7) / 8, 256>>>(KV, ca_null + (size_t)l * 2 * NHEAD * DHEAD,
                                                              ca_ks + l * DHEAD, K, V, NCTX);
        flash_kernel<<<dim3(NTOK / 128, NHEAD), 256, FLASH_SMEM>>>(QN, K, V, O, NTOK, NCTX + 1);
        gemm_mma_kernel<<<dim3(8, 12), 256, GEMM_SMEM>>>(O, ca_wo + (size_t)l * DMODEL * DMODEL, H, NTOK, DMODEL, DMODEL, 1);

        // ------- GEGLU feedforward -------
        ln_kernel<<<NTOK, 256>>>(H, ff_g1 + (size_t)l * DMODEL, XN, DMODEL);
        gemm_mma_kernel<<<dim3((FF2 + 127) / 128, 12), 256, GEMM_SMEM>>>(XN, ff_w1 + (size_t)l * DMODEL * FF2, HH, NTOK, FF2, DMODEL, 0);
        geglu_ln_kernel<<<NTOK, 256>>>(HH, ff_g2 + (size_t)l * FFI, GN);
        gemm_mma_kernel<<<dim3(8, 12), 256, GEMM_SMEM>>>(GN, ff_w2 + (size_t)l * FFI * DMODEL, H, NTOK, DMODEL, FFI, 1);
    }

    // ------- final norm + logits -------
    ln_kernel<<<NTOK, 256>>>(H, final_g, XN, DMODEL);
    gemm_mma_kernel<<<dim3(VOCAB / 128, 12), 256, GEMM_SMEM>>>(XN, w_logits, out, NTOK, VOCAB, DMODEL, 0);
}

// round 8
// speedup vs baseline: 2.4397x; 1.3474x over previous
#include <cuda_runtime.h>
#include <cuda_bf16.h>
#include <math.h>
#include <stdint.h>

// ---------------- model dims ----------------
#define NLAYER 4
#define DMODEL 1024
#define NHEAD  16
#define DHEAD  64
#define NTOK   1536
#define NCTX   512
#define VOCAB  8192
#define FFI    2730          // GEGLU inner
#define FF2    5460          // 2*FFI
#define FFIP   2752          // FFI padded to 64

// ---------------- weight scratch offsets (padded, transposed [n][k] bf16) ----------------
#define W_WQ    0ull
#define W_WKV   1048576ull
#define W_WO    3145728ull
#define W_CWQ   4194304ull
#define W_CWKV  5242880ull
#define W_CWO   7340032ull
#define W_FF1   8388608ull
#define W_FF2   14024704ull
#define LBLK    16842752ull
#define W_LOG   67371008ull
#define WTOT    75759616ull

// ---------------- scratch (device globals; no allocation allowed) ----------------
__device__ float g_H  [NTOK * DMODEL];
__device__ float g_Q  [NTOK * DMODEL];
__device__ float g_KV [NTOK * 2 * DMODEL];
__device__ float g_QN [NHEAD * NTOK * DHEAD];
__device__ float g_K  [NHEAD * (NTOK + 1) * DHEAD];
__device__ float g_V  [NHEAD * (NTOK + 1) * DHEAD];
__device__ float g_HH [NTOK * FF2];

__device__ __align__(128) __nv_bfloat16 g_WH[WTOT];
__device__ __align__(128) __nv_bfloat16 g_WL[WTOT];
__device__ __align__(128) __nv_bfloat16 g_XNh[NTOK * DMODEL],  g_XNl[NTOK * DMODEL];
__device__ __align__(128) __nv_bfloat16 g_CTXh[NCTX * DMODEL], g_CTXl[NCTX * DMODEL];
__device__ __align__(128) __nv_bfloat16 g_Oh[NTOK * DMODEL],   g_Ol[NTOK * DMODEL];
__device__ __align__(128) __nv_bfloat16 g_GNh[NTOK * FFIP],    g_GNl[NTOK * FFIP];

// ---------------- helpers ----------------
__device__ __forceinline__ uint32_t smem_u32(const void* p) {
    uint32_t a;
    asm("{ .reg .u64 t; cvta.to.shared.u64 t, %1; cvt.u32.u64 %0, t; }" : "=r"(a) : "l"(p));
    return a;
}
__device__ __forceinline__ void split2(float f0, float f1, uint32_t& hi, uint32_t& lo) {
    __nv_bfloat16 h0 = __float2bfloat16(f0), h1 = __float2bfloat16(f1);
    float r0 = f0 - __bfloat162float(h0), r1 = f1 - __bfloat162float(h1);
    __nv_bfloat16 l0 = __float2bfloat16(r0), l1 = __float2bfloat16(r1);
    hi = (uint32_t)__bfloat16_as_ushort(h0) | ((uint32_t)__bfloat16_as_ushort(h1) << 16);
    lo = (uint32_t)__bfloat16_as_ushort(l0) | ((uint32_t)__bfloat16_as_ushort(l1) << 16);
}
__device__ __forceinline__ void ldsm4(uint32_t* r, uint32_t addr) {
    asm volatile("ldmatrix.sync.aligned.m8n8.x4.shared.b16 {%0,%1,%2,%3}, [%4];"
                 : "=r"(r[0]), "=r"(r[1]), "=r"(r[2]), "=r"(r[3]) : "r"(addr));
}
__device__ __forceinline__ void mma16816(float* c, const uint32_t* a, uint32_t b0, uint32_t b1) {
    asm volatile(
        "mma.sync.aligned.m16n8k16.row.col.f32.bf16.bf16.f32 "
        "{%0,%1,%2,%3}, {%4,%5,%6,%7}, {%8,%9}, {%0,%1,%2,%3};"
        : "+f"(c[0]), "+f"(c[1]), "+f"(c[2]), "+f"(c[3])
        : "r"(a[0]), "r"(a[1]), "r"(a[2]), "r"(a[3]), "r"(b0), "r"(b1));
}
__device__ __forceinline__ void cp16(uint32_t s, const void* g) {
    asm volatile("cp.async.cg.shared.global [%0], [%1], 16;\n" :: "r"(s), "l"(g));
}

// ---------------- weight convert: W[k][n] fp32 -> Wt_hi/lo [n][k_pad] bf16, zero-padded ----
__global__ void convw_kernel(const float* __restrict__ W, __nv_bfloat16* __restrict__ TH,
                             __nv_bfloat16* __restrict__ TL, int K, int N, int k_pad) {
    __shared__ float t[32][33];
    int tid = threadIdx.x;
    int tx = tid & 31, ty = tid >> 5;           // 32 x 8 loaders
    int kb = blockIdx.y * 32, nb = blockIdx.x * 32;
    #pragma unroll
    for (int r = 0; r < 4; r++) {
        int k = kb + ty + 8 * r, n = nb + tx;
        t[ty + 8 * r][tx] = (k < K && n < N) ? W[(size_t)k * N + n] : 0.f;
    }
    __syncthreads();
    int nrow = tid >> 3, kp = tid & 7;          // 32 n-rows x 8 threads (2 k-pairs each)
    #pragma unroll
    for (int w = 0; w < 2; w++) {
        int kk = (kp + 8 * w) * 2;
        float f0 = t[kk][nrow], f1 = t[kk + 1][nrow];
        uint32_t hi, lo;
        split2(f0, f1, hi, lo);
        size_t o = (size_t)(nb + nrow) * k_pad + kb + kk;
        *(uint32_t*)&TH[o] = hi;
        *(uint32_t*)&TL[o] = lo;
    }
}

// ---------------- tensor-core GEMM: C[M,N] = A @ B^T (+C), bf16 hi/lo inputs ----------
// A: [M][lda] bf16 pair; B: [n_pad][ldb] bf16 pair (pre-transposed). 128x128 CTA tile,
// BK=64, cp.async double buffer (2 x 64KB), 8 warps (32x64 warp tile), 3-term split MMA.
__global__ __launch_bounds__(256, 1)
void gemm_bf16_kernel(const __nv_bfloat16* __restrict__ AH, const __nv_bfloat16* __restrict__ AL,
                      const __nv_bfloat16* __restrict__ BH, const __nv_bfloat16* __restrict__ BL,
                      float* __restrict__ C, int M, int N, int lda, int ldb,
                      int ktiles, int addC) {
    extern __shared__ char smraw[];
    uint32_t sbase = smem_u32(smraw);
    int tid = threadIdx.x, warp = tid >> 5, lane = tid & 31;
    int wm = (warp >> 1) * 32, wn = (warp & 1) * 64;
    int m0 = blockIdx.y * 128, n0 = blockIdx.x * 128;

    float acc[2][8][4];
    #pragma unroll
    for (int mi = 0; mi < 2; mi++)
        #pragma unroll
        for (int ni = 0; ni < 8; ni++)
            acc[mi][ni][0] = acc[mi][ni][1] = acc[mi][ni][2] = acc[mi][ni][3] = 0.f;

    int srow = tid >> 3, skc = tid & 7;   // this thread stages rows srow, srow+32, +64, +96
    uint32_t soff0 = (uint32_t)srow * 128 + (uint32_t)((skc ^ (srow & 7)) << 4);

    auto stage = [&](int t, int buf) {
        int k0 = t << 6;
        uint32_t sb = sbase + (uint32_t)buf * 65536u;
        #pragma unroll
        for (int i = 0; i < 4; i++) {
            int row = srow + i * 32;
            uint32_t soff = (uint32_t)row * 128 + (uint32_t)((skc ^ (row & 7)) << 4);
            size_t ao = (size_t)(m0 + row) * lda + k0 + skc * 8;
            size_t bo = (size_t)(n0 + row) * ldb + k0 + skc * 8;
            cp16(sb + soff,          AH + ao);
            cp16(sb + 16384 + soff,  AL + ao);
            cp16(sb + 32768 + soff,  BH + bo);
            cp16(sb + 49152 + soff,  BL + bo);
        }
        asm volatile("cp.async.commit_group;\n" ::: "memory");
    };
    (void)soff0;

    stage(0, 0);
    for (int t = 0; t < ktiles; t++) {
        int buf = t & 1;
        asm volatile("cp.async.wait_group 0;\n" ::: "memory");
        __syncthreads();
        if (t + 1 < ktiles) stage(t + 1, buf ^ 1);

        uint32_t aHb = sbase + (uint32_t)buf * 65536u;
        uint32_t aLb = aHb + 16384, bHb = aHb + 32768, bLb = aHb + 49152;
        #pragma unroll
        for (int ks = 0; ks < 4; ks++) {
            uint32_t ah[2][4], al[2][4];
            #pragma unroll
            for (int mi = 0; mi < 2; mi++) {
                int row = wm + mi * 16 + (lane & 15);
                int c = ks * 2 + (lane >> 4);
                uint32_t off = (uint32_t)row * 128 + (uint32_t)((c ^ (row & 7)) << 4);
                ldsm4(ah[mi], aHb + off);
                ldsm4(al[mi], aLb + off);
            }
            #pragma unroll
            for (int np = 0; np < 4; np++) {
                uint32_t bh[4], bl[4];
                int row = wn + np * 16 + (lane & 15);
                int c = ks * 2 + (lane >> 4);
                uint32_t off = (uint32_t)row * 128 + (uint32_t)((c ^ (row & 7)) << 4);
                ldsm4(bh, bHb + off);
                ldsm4(bl, bLb + off);
                #pragma unroll
                for (int mi = 0; mi < 2; mi++) {
                    mma16816(acc[mi][2 * np],     ah[mi], bh[0], bh[2]);
                    mma16816(acc[mi][2 * np],     al[mi], bh[0], bh[2]);
                    mma16816(acc[mi][2 * np],     ah[mi], bl[0], bl[2]);
                    mma16816(acc[mi][2 * np + 1], ah[mi], bh[1], bh[3]);
                    mma16816(acc[mi][2 * np + 1], al[mi], bh[1], bh[3]);
                    mma16816(acc[mi][2 * np + 1], ah[mi], bl[1], bl[3]);
                }
            }
        }
        __syncthreads();
    }

    // ---- epilogue ----
    int gid = lane >> 2, tig = lane & 3;
    #pragma unroll
    for (int mi = 0; mi < 2; mi++) {
        #pragma unroll
        for (int ni = 0; ni < 8; ni++) {
            int row = m0 + wm + mi * 16 + gid;
            int col = n0 + wn + ni * 8 + tig * 2;
            if (col + 1 < N && row < M) {
                float* cp = &C[(size_t)row * N + col];
                float2 v = make_float2(acc[mi][ni][0], acc[mi][ni][1]);
                if (addC) { float2 o = *(float2*)cp; v.x += o.x; v.y += o.y; }
                *(float2*)cp = v;
                float* cp8 = cp + 8 * (size_t)N;
                float2 w = make_float2(acc[mi][ni][2], acc[mi][ni][3]);
                if (addC) { float2 o = *(float2*)cp8; w.x += o.x; w.y += o.y; }
                *(float2*)cp8 = w;
            }
        }
    }
}

// ---------------- embeddings ----------------
__global__ void embed_img_kernel(const int* __restrict__ ids, const float* __restrict__ te,
                                 const float* __restrict__ pe, float* __restrict__ out) {
    int i = blockIdx.x * blockDim.x + threadIdx.x;
    if (i >= NTOK * DMODEL) return;
    int n = i >> 10, d = i & 1023;
    out[i] = te[(size_t)ids[n] * DMODEL + d] + pe[i];
}
__global__ void embed_ctx_kernel(const int* __restrict__ ids, const float* __restrict__ te,
                                 const float* __restrict__ pe,
                                 __nv_bfloat16* __restrict__ Yh, __nv_bfloat16* __restrict__ Yl) {
    int p = blockIdx.x * blockDim.x + threadIdx.x;
    if (p >= NCTX * DMODEL / 2) return;
    int i = p * 2;
    int n = i >> 10, d = i & 1023;
    const float* row = te + (size_t)ids[n] * DMODEL;
    float f0 = row[d] + pe[i];
    float f1 = row[d + 1] + pe[i + 1];
    uint32_t hi, lo;
    split2(f0, f1, hi, lo);
    *(uint32_t*)&Yh[i] = hi;
    *(uint32_t*)&Yl[i] = lo;
}

// ---------------- LayerNorm -> bf16 hi/lo (C = 1024 fixed) ----------------
__global__ void ln_kernel(const float* __restrict__ X, const float* __restrict__ g,
                          __nv_bfloat16* __restrict__ Yh, __nv_bfloat16* __restrict__ Yl) {
    int row = blockIdx.x;
    const float* x = X + (size_t)row * DMODEL;
    int tid = threadIdx.x;
    float v[4], s1 = 0.f, s2 = 0.f;
    #pragma unroll
    for (int j = 0; j < 4; j++) { v[j] = x[tid * 4 + j]; s1 += v[j]; s2 += v[j] * v[j]; }
    __shared__ float red[512];
    red[tid] = s1; red[256 + tid] = s2;
    __syncthreads();
    for (int s = 128; s > 0; s >>= 1) {
        if (tid < s) { red[tid] += red[tid + s]; red[256 + tid] += red[256 + tid + s]; }
        __syncthreads();
    }
    float mean = red[0] / DMODEL;
    float var  = red[256] / DMODEL - mean * mean;
    float inv  = rsqrtf(var + 1e-5f);
    float y[4];
    #pragma unroll
    for (int j = 0; j < 4; j++) y[j] = (v[j] - mean) * inv * g[tid * 4 + j];
    uint32_t h0, l0, h1, l1;
    split2(y[0], y[1], h0, l0);
    split2(y[2], y[3], h1, l1);
    size_t o = (size_t)row * DMODEL + tid * 4;
    *(uint2*)&Yh[o] = make_uint2(h0, h1);
    *(uint2*)&Yl[o] = make_uint2(l0, l1);
}

// ---------------- fused GEGLU + LayerNorm -> bf16 hi/lo [row][FFIP] ----------------
__global__ void geglu_ln_kernel(const float* __restrict__ HH, const float* __restrict__ g2,
                                __nv_bfloat16* __restrict__ Yh, __nv_bfloat16* __restrict__ Yl) {
    int row = blockIdx.x;
    const float* h = HH + (size_t)row * FF2;
    int tid = threadIdx.x;
    __shared__ float buf[FFI];
    __shared__ float red[512];
    float s1 = 0.f, s2 = 0.f;
    for (int c = tid; c < FFI; c += 256) {
        float a = h[c], gate = h[FFI + c];
        float v = gate * (0.5f * a * (1.0f + erff(a * 0.70710678118654752f)));
        buf[c] = v; s1 += v; s2 += v * v;
    }
    red[tid] = s1; red[256 + tid] = s2;
    __syncthreads();
    for (int s = 128; s > 0; s >>= 1) {
        if (tid < s) { red[tid] += red[tid + s]; red[256 + tid] += red[256 + tid + s]; }
        __syncthreads();
    }
    float mean = red[0] / FFI;
    float var  = red[256] / FFI - mean * mean;
    float inv  = rsqrtf(var + 1e-5f);
    for (int q = tid; q < FFIP / 4; q += 256) {
        int c = q * 4;
        float y[4];
        #pragma unroll
        for (int j = 0; j < 4; j++) {
            int cc = c + j;
            y[j] = (cc < FFI) ? (buf[cc] - mean) * inv * g2[cc] : 0.f;
        }
        uint32_t h0, l0, h1, l1;
        split2(y[0], y[1], h0, l0);
        split2(y[2], y[3], h1, l1);
        size_t o = (size_t)row * FFIP + c;
        *(uint2*)&Yh[o] = make_uint2(h0, h1);
        *(uint2*)&Yl[o] = make_uint2(l0, l1);
    }
}

// ---------------- Q prep ----------------
__global__ void prep_q_kernel(const float* __restrict__ Qin, const float* __restrict__ qs,
                              float* __restrict__ QN, int Nq) {
    int gw = (blockIdx.x * blockDim.x + threadIdx.x) >> 5;
    int lane = threadIdx.x & 31;
    if (gw >= NHEAD * Nq) return;
    int h = gw / Nq, n = gw % Nq;
    const float* src = Qin + (size_t)n * DMODEL + h * DHEAD;
    float v0 = src[lane], v1 = src[lane + 32];
    float ss = v0 * v0 + v1 * v1;
    #pragma unroll
    for (int s = 16; s; s >>= 1) ss += __shfl_xor_sync(0xffffffffu, ss, s);
    float inv = 1.0f / fmaxf(sqrtf(ss), 1e-12f);
    float* dst = QN + ((size_t)h * Nq + n) * DHEAD;
    dst[lane]      = v0 * inv * qs[lane] * 8.0f;
    dst[lane + 32] = v1 * inv * qs[lane + 32] * 8.0f;
}

// ---------------- KV prep ----------------
__global__ void prep_kv_kernel(const float* __restrict__ KVin, const float* __restrict__ nullp,
                               const float* __restrict__ ks, float* __restrict__ Ko,
                               float* __restrict__ Vo, int Nt) {
    int NK = Nt + 1;
    int gw = (blockIdx.x * blockDim.x + threadIdx.x) >> 5;
    int lane = threadIdx.x & 31;
    if (gw >= NHEAD * NK) return;
    int h = gw / NK, j = gw % NK;
    float k0, k1, v0, v1;
    if (j == 0) {
        k0 = nullp[h * DHEAD + lane];
        k1 = nullp[h * DHEAD + lane + 32];
        v0 = nullp[NHEAD * DHEAD + h * DHEAD + lane];
        v1 = nullp[NHEAD * DHEAD + h * DHEAD + lane + 32];
    } else {
        const float* src = KVin + (size_t)(j - 1) * (2 * DMODEL) + h * DHEAD;
        k0 = src[lane];          k1 = src[lane + 32];
        v0 = src[DMODEL + lane]; v1 = src[DMODEL + lane + 32];
    }
    float ss = k0 * k0 + k1 * k1;
    #pragma unroll
    for (int s = 16; s; s >>= 1) ss += __shfl_xor_sync(0xffffffffu, ss, s);
    float inv = 1.0f / fmaxf(sqrtf(ss), 1e-12f);
    size_t base = ((size_t)h * NK + j) * DHEAD;
    Ko[base + lane]      = k0 * inv * ks[lane];
    Ko[base + lane + 32] = k1 * inv * ks[lane + 32];
    Vo[base + lane]      = v0;
    Vo[base + lane + 32] = v1;
}

// ---------------- fused flash attention (scalar; epilogue emits bf16 hi/lo) ----------------
__global__ __launch_bounds__(256, 2)
void flash_kernel(const float* __restrict__ Q, const float* __restrict__ K,
                  const float* __restrict__ V,
                  __nv_bfloat16* __restrict__ Oh, __nv_bfloat16* __restrict__ Ol,
                  int Nq, int NK) {
    extern __shared__ float sm[];
    float* Qs = sm;
    float* KT = sm + 8192;
    float* Ps = sm + 12288;
    int h  = blockIdx.y;
    int qb = blockIdx.x * 128;
    int tid = threadIdx.x;
    int tx = tid & 15, ty = tid >> 4;
    int r0 = ty * 8, c0 = tx * 4;

    const float* Qg = Q + ((size_t)h * Nq + qb) * DHEAD;
    for (int i = tid * 4; i < 8192; i += 1024)
        *(float4*)&Qs[i] = *(const float4*)&Qg[i];

    float o[8][4];
    float mrow[8], lrow[8];
    #pragma unroll
    for (int i = 0; i < 8; i++) {
        mrow[i] = -1e30f; lrow[i] = 0.f;
        o[i][0] = o[i][1] = o[i][2] = o[i][3] = 0.f;
    }

    int ntiles = (NK + 63) >> 6;
    int kj = tid & 63, kd = (tid >> 6) << 4;

    for (int t = 0; t < ntiles; t++) {
        int kb = t << 6;
        __syncthreads();
        {
            bool valid = (kb + kj) < NK;
            const float* Kg = K + ((size_t)h * NK + kb + kj) * DHEAD;
            #pragma unroll
            for (int r = 0; r < 4; r++) {
                int d0 = kd + r * 4;
                float4 g = valid ? *(const float4*)&Kg[d0] : make_float4(0, 0, 0, 0);
                KT[(d0 + 0) * 64 + kj] = g.x;
                KT[(d0 + 1) * 64 + kj] = g.y;
                KT[(d0 + 2) * 64 + kj] = g.z;
                KT[(d0 + 3) * 64 + kj] = g.w;
            }
        }
        __syncthreads();

        float acc[8][4];
        #pragma unroll
        for (int i = 0; i < 8; i++) acc[i][0] = acc[i][1] = acc[i][2] = acc[i][3] = 0.f;
        #pragma unroll
        for (int d = 0; d < 64; d += 4) {
            float4 k4[4];
            #pragma unroll
            for (int j = 0; j < 4; j++) k4[j] = *(float4*)&KT[(d + j) * 64 + c0];
            #pragma unroll
            for (int i = 0; i < 8; i++) {
                float4 q4 = *(float4*)&Qs[(r0 + i) * 64 + d];
                acc[i][0] += q4.x * k4[0].x + q4.y * k4[1].x + q4.z * k4[2].x + q4.w * k4[3].x;
                acc[i][1] += q4.x * k4[0].y + q4.y * k4[1].y + q4.z * k4[2].y + q4.w * k4[3].y;
                acc[i][2] += q4.x * k4[0].z + q4.y * k4[1].z + q4.z * k4[2].z + q4.w * k4[3].z;
                acc[i][3] += q4.x * k4[0].w + q4.y * k4[1].w + q4.z * k4[2].w + q4.w * k4[3].w;
            }
        }
        if (kb + 64 > NK) {
            #pragma unroll
            for (int j = 0; j < 4; j++)
                if (kb + c0 + j >= NK)
                    #pragma unroll
                    for (int i = 0; i < 8; i++) acc[i][j] = -1e30f;
        }
        float tmax[8];
        #pragma unroll
        for (int i = 0; i < 8; i++)
            tmax[i] = fmaxf(fmaxf(acc[i][0], acc[i][1]), fmaxf(acc[i][2], acc[i][3]));
        #pragma unroll
        for (int s = 1; s < 16; s <<= 1)
            #pragma unroll
            for (int i = 0; i < 8; i++)
                tmax[i] = fmaxf(tmax[i], __shfl_xor_sync(0xffffffffu, tmax[i], s, 32));
        float corr[8];
        #pragma unroll
        for (int i = 0; i < 8; i++) {
            float mnew = fmaxf(mrow[i], tmax[i]);
            corr[i] = expf(mrow[i] - mnew);
            mrow[i] = mnew;
        }
        float rsum[8];
        #pragma unroll
        for (int i = 0; i < 8; i++) {
            float s = 0.f;
            #pragma unroll
            for (int j = 0; j < 4; j++) {
                float p = expf(acc[i][j] - mrow[i]);
                acc[i][j] = p; s += p;
            }
            rsum[i] = s;
        }
        #pragma unroll
        for (int s = 1; s < 16; s <<= 1)
            #pragma unroll
            for (int i = 0; i < 8; i++)
                rsum[i] += __shfl_xor_sync(0xffffffffu, rsum[i], s, 32);
        #pragma unroll
        for (int i = 0; i < 8; i++) {
            lrow[i] = lrow[i] * corr[i] + rsum[i];
            o[i][0] *= corr[i]; o[i][1] *= corr[i]; o[i][2] *= corr[i]; o[i][3] *= corr[i];
            *(float4*)&Ps[(r0 + i) * 64 + c0] = make_float4(acc[i][0], acc[i][1], acc[i][2], acc[i][3]);
        }
        __syncthreads();
        for (int i = tid * 4; i < 4096; i += 1024) {
            int j = i >> 6;
            *(float4*)&KT[i] = (kb + j < NK)
                ? *(const float4*)&V[((size_t)h * NK + kb + j) * DHEAD + (i & 63)]
                : make_float4(0, 0, 0, 0);
        }
        __syncthreads();
        #pragma unroll
        for (int jk = 0; jk < 64; jk += 4) {
            float4 v4[4];
            #pragma unroll
            for (int jj = 0; jj < 4; jj++) v4[jj] = *(float4*)&KT[(jk + jj) * 64 + c0];
            #pragma unroll
            for (int i = 0; i < 8; i++) {
                float4 p4 = *(float4*)&Ps[(r0 + i) * 64 + jk];
                o[i][0] += p4.x * v4[0].x + p4.y * v4[1].x + p4.z * v4[2].x + p4.w * v4[3].x;
                o[i][1] += p4.x * v4[0].y + p4.y * v4[1].y + p4.z * v4[2].y + p4.w * v4[3].y;
                o[i][2] += p4.x * v4[0].z + p4.y * v4[1].z + p4.z * v4[2].z + p4.w * v4[3].z;
                o[i][3] += p4.x * v4[0].w + p4.y * v4[1].w + p4.z * v4[2].w + p4.w * v4[3].w;
            }
        }
    }
    #pragma unroll
    for (int i = 0; i < 8; i++) {
        float inv = 1.f / lrow[i];
        int n = qb + r0 + i;
        uint32_t h0, l0, h1, l1;
        split2(o[i][0] * inv, o[i][1] * inv, h0, l0);
        split2(o[i][2] * inv, o[i][3] * inv, h1, l1);
        size_t off = (size_t)n * DMODEL + h * DHEAD + c0;
        *(uint2*)&Oh[off] = make_uint2(h0, h1);
        *(uint2*)&Ol[off] = make_uint2(l0, l1);
    }
}

// ---------------- host orchestration ----------------
extern "C" void kernel_launch(void* const* d_in, const int* in_sizes, int n_in,
                              void* d_out, int out_size) {
    (void)in_sizes; (void)n_in; (void)out_size;
    const int*   x_ids    = (const int*)d_in[0];
    const int*   cond_ids = (const int*)d_in[1];
    const float* token_emb = (const float*)d_in[2];
    const float* pos_emb   = (const float*)d_in[3];
    const float* cte       = (const float*)d_in[4];
    const float* cpe       = (const float*)d_in[5];
    const float* sa_g    = (const float*)d_in[6];
    const float* sa_wq   = (const float*)d_in[7];
    const float* sa_wkv  = (const float*)d_in[8];
    const float* sa_null = (const float*)d_in[9];
    const float* sa_qs   = (const float*)d_in[10];
    const float* sa_ks   = (const float*)d_in[11];
    const float* sa_wo   = (const float*)d_in[12];
    const float* ca_g    = (const float*)d_in[13];
    const float* ca_wq   = (const float*)d_in[14];
    const float* ca_wkv  = (const float*)d_in[15];
    const float* ca_null = (const float*)d_in[16];
    const float* ca_qs   = (const float*)d_in[17];
    const float* ca_ks   = (const float*)d_in[18];
    const float* ca_wo   = (const float*)d_in[19];
    const float* ff_g1   = (const float*)d_in[20];
    const float* ff_w1   = (const float*)d_in[21];
    const float* ff_g2   = (const float*)d_in[22];
    const float* ff_w2   = (const float*)d_in[23];
    const float* final_g  = (const float*)d_in[24];
    const float* w_logits = (const float*)d_in[25];
    float* out = (float*)d_out;

    float *H, *Q, *KV, *QN, *K, *V, *HH;
    __nv_bfloat16 *WH, *WL, *XNh, *XNl, *CTXh, *CTXl, *Oh, *Ol, *GNh, *GNl;
    cudaGetSymbolAddress((void**)&H,   g_H);
    cudaGetSymbolAddress((void**)&Q,   g_Q);
    cudaGetSymbolAddress((void**)&KV,  g_KV);
    cudaGetSymbolAddress((void**)&QN,  g_QN);
    cudaGetSymbolAddress((void**)&K,   g_K);
    cudaGetSymbolAddress((void**)&V,   g_V);
    cudaGetSymbolAddress((void**)&HH,  g_HH);
    cudaGetSymbolAddress((void**)&WH,  g_WH);
    cudaGetSymbolAddress((void**)&WL,  g_WL);
    cudaGetSymbolAddress((void**)&XNh, g_XNh);
    cudaGetSymbolAddress((void**)&XNl, g_XNl);
    cudaGetSymbolAddress((void**)&CTXh, g_CTXh);
    cudaGetSymbolAddress((void**)&CTXl, g_CTXl);
    cudaGetSymbolAddress((void**)&Oh,  g_Oh);
    cudaGetSymbolAddress((void**)&Ol,  g_Ol);
    cudaGetSymbolAddress((void**)&GNh, g_GNh);
    cudaGetSymbolAddress((void**)&GNl, g_GNl);

    const int FLASH_SMEM = 20480 * 4;    // 80KB
    const int GEMM_SMEM  = 131072;       // 128KB (2 x 64KB stage buffers)
    cudaFuncSetAttribute(flash_kernel, cudaFuncAttributeMaxDynamicSharedMemorySize, FLASH_SMEM);
    cudaFuncSetAttribute(gemm_bf16_kernel, cudaFuncAttributeMaxDynamicSharedMemorySize, GEMM_SMEM);

    // ---- weight conversion (once per launch; graph-replayed) ----
    auto convw = [&](const float* W, size_t off, int Kd, int Nd, int k_pad, int n_pad) {
        convw_kernel<<<dim3(n_pad / 32, k_pad / 32), 256>>>(W, WH + off, WL + off, Kd, Nd, k_pad);
    };
    for (int l = 0; l < NLAYER; l++) {
        size_t lb = (size_t)l * LBLK;
        convw(sa_wq  + (size_t)l * DMODEL * DMODEL,     lb + W_WQ,   1024, 1024, 1024, 1024);
        convw(sa_wkv + (size_t)l * DMODEL * 2 * DMODEL, lb + W_WKV,  1024, 2048, 1024, 2048);
        convw(sa_wo  + (size_t)l * DMODEL * DMODEL,     lb + W_WO,   1024, 1024, 1024, 1024);
        convw(ca_wq  + (size_t)l * DMODEL * DMODEL,     lb + W_CWQ,  1024, 1024, 1024, 1024);
        convw(ca_wkv + (size_t)l * DMODEL * 2 * DMODEL, lb + W_CWKV, 1024, 2048, 1024, 2048);
        convw(ca_wo  + (size_t)l * DMODEL * DMODEL,     lb + W_CWO,  1024, 1024, 1024, 1024);
        convw(ff_w1  + (size_t)l * DMODEL * FF2,        lb + W_FF1,  1024, FF2,  1024, 5504);
        convw(ff_w2  + (size_t)l * FFI * DMODEL,        lb + W_FF2,  FFI,  1024, FFIP, 1024);
    }
    convw(w_logits, W_LOG, 1024, VOCAB, 1024, VOCAB);

    embed_img_kernel<<<(NTOK * DMODEL) / 256, 256>>>(x_ids, token_emb, pos_emb, H);
    embed_ctx_kernel<<<(NCTX * DMODEL / 2) / 256, 256>>>(cond_ids, cte, cpe, CTXh, CTXl);

    auto gemm = [&](const __nv_bfloat16* aH, const __nv_bfloat16* aL, size_t woff,
                    float* Cp, int M, int N, int lda, int ldb, int ktiles, int addC,
                    int gx, int gy) {
        gemm_bf16_kernel<<<dim3(gx, gy), 256, GEMM_SMEM>>>(aH, aL, WH + woff, WL + woff,
                                                           Cp, M, N, lda, ldb, ktiles, addC);
    };

    for (int l = 0; l < NLAYER; l++) {
        size_t lb = (size_t)l * LBLK;
        // ------- self attention -------
        ln_kernel<<<NTOK, 256>>>(H, sa_g + (size_t)l * DMODEL, XNh, XNl);
        gemm(XNh, XNl, lb + W_WQ,  Q,  NTOK, 1024, 1024, 1024, 16, 0, 8, 12);
        gemm(XNh, XNl, lb + W_WKV, KV, NTOK, 2048, 1024, 1024, 16, 0, 16, 12);
        prep_q_kernel<<<(NHEAD * NTOK + 7) / 8, 256>>>(Q, sa_qs + l * DHEAD, QN, NTOK);
        prep_kv_kernel<<<(NHEAD * (NTOK + 1) + 7) / 8, 256>>>(KV, sa_null + (size_t)l * 2 * NHEAD * DHEAD,
                                                              sa_ks + l * DHEAD, K, V, NTOK);
        flash_kernel<<<dim3(NTOK / 128, NHEAD), 256, FLASH_SMEM>>>(QN, K, V, Oh, Ol, NTOK, NTOK + 1);
        gemm(Oh, Ol, lb + W_WO, H, NTOK, 1024, 1024, 1024, 16, 1, 8, 12);

        // ------- cross attention -------
        ln_kernel<<<NTOK, 256>>>(H, ca_g + (size_t)l * DMODEL, XNh, XNl);
        gemm(XNh, XNl, lb + W_CWQ, Q, NTOK, 1024, 1024, 1024, 16, 0, 8, 12);
        gemm(CTXh, CTXl, lb + W_CWKV, KV, NCTX, 2048, 1024, 1024, 16, 0, 16, 4);
        prep_q_kernel<<<(NHEAD * NTOK + 7) / 8, 256>>>(Q, ca_qs + l * DHEAD, QN, NTOK);
        prep_kv_kernel<<<(NHEAD * (NCTX + 1) + 7) / 8, 256>>>(KV, ca_null + (size_t)l * 2 * NHEAD * DHEAD,
                                                              ca_ks + l * DHEAD, K, V, NCTX);
        flash_kernel<<<dim3(NTOK / 128, NHEAD), 256, FLASH_SMEM>>>(QN, K, V, Oh, Ol, NTOK, NCTX + 1);
        gemm(Oh, Ol, lb + W_CWO, H, NTOK, 1024, 1024, 1024, 16, 1, 8, 12);

        // ------- GEGLU feedforward -------
        ln_kernel<<<NTOK, 256>>>(H, ff_g1 + (size_t)l * DMODEL, XNh, XNl);
        gemm(XNh, XNl, lb + W_FF1, HH, NTOK, FF2, 1024, 1024, 16, 0, 43, 12);
        geglu_ln_kernel<<<NTOK, 256>>>(HH, ff_g2 + (size_t)l * FFI, GNh, GNl);
        gemm(GNh, GNl, lb + W_FF2, H, NTOK, 1024, FFIP, FFIP, 43, 1, 8, 12);
    }

    // ------- final norm + logits -------
    ln_kernel<<<NTOK, 256>>>(H, final_g, XNh, XNl);
    gemm(XNh, XNl, W_LOG, out, NTOK, VOCAB, 1024, 1024, 16, 0, 64, 12);
}

// round 10
// speedup vs baseline: 2.4533x; 1.0056x over previous
#include <cuda_runtime.h>
#include <cuda_bf16.h>
#include <math.h>
#include <stdint.h>

// ---------------- model dims ----------------
#define NLAYER 4
#define DMODEL 1024
#define NHEAD  16
#define DHEAD  64
#define NTOK   1536
#define NCTX   512
#define VOCAB  8192
#define FFI    2730          // GEGLU inner
#define FF2    5460          // 2*FFI
#define FFIP   2752          // FFI padded to 64

// ---------------- weight scratch offsets (padded, transposed [n][k] bf16) ----------------
#define W_WQ    0ull
#define W_WKV   1048576ull
#define W_WO    3145728ull
#define W_CWQ   4194304ull
#define W_CWKV  5242880ull
#define W_CWO   7340032ull
#define W_FF1   8388608ull
#define W_FF2   14024704ull
#define LBLK    16842752ull
#define W_LOG   67371008ull
#define WTOT    75759616ull

// ---------------- scratch (device globals; no allocation allowed) ----------------
__device__ float g_H  [NTOK * DMODEL];
__device__ float g_Q  [NTOK * DMODEL];
__device__ float g_KV [NTOK * 2 * DMODEL];
__device__ float g_QN [NHEAD * NTOK * DHEAD];
__device__ float g_K  [NHEAD * (NTOK + 1) * DHEAD];
__device__ float g_V  [NHEAD * (NTOK + 1) * DHEAD];
__device__ float g_HH [NTOK * FF2];

__device__ __align__(128) __nv_bfloat16 g_WH[WTOT];
__device__ __align__(128) __nv_bfloat16 g_WL[WTOT];
__device__ __align__(128) __nv_bfloat16 g_XNh[NTOK * DMODEL],  g_XNl[NTOK * DMODEL];
__device__ __align__(128) __nv_bfloat16 g_CTXh[NCTX * DMODEL], g_CTXl[NCTX * DMODEL];
__device__ __align__(128) __nv_bfloat16 g_Oh[NTOK * DMODEL],   g_Ol[NTOK * DMODEL];
__device__ __align__(128) __nv_bfloat16 g_GNh[NTOK * FFIP],    g_GNl[NTOK * FFIP];

// ---------------- helpers ----------------
__device__ __forceinline__ uint32_t smem_u32(const void* p) {
    uint32_t a;
    asm("{ .reg .u64 t; cvta.to.shared.u64 t, %1; cvt.u32.u64 %0, t; }" : "=r"(a) : "l"(p));
    return a;
}
__device__ __forceinline__ void split2(float f0, float f1, uint32_t& hi, uint32_t& lo) {
    __nv_bfloat16 h0 = __float2bfloat16(f0), h1 = __float2bfloat16(f1);
    float r0 = f0 - __bfloat162float(h0), r1 = f1 - __bfloat162float(h1);
    __nv_bfloat16 l0 = __float2bfloat16(r0), l1 = __float2bfloat16(r1);
    hi = (uint32_t)__bfloat16_as_ushort(h0) | ((uint32_t)__bfloat16_as_ushort(h1) << 16);
    lo = (uint32_t)__bfloat16_as_ushort(l0) | ((uint32_t)__bfloat16_as_ushort(l1) << 16);
}
__device__ __forceinline__ void ldsm4(uint32_t* r, uint32_t addr) {
    asm volatile("ldmatrix.sync.aligned.m8n8.x4.shared.b16 {%0,%1,%2,%3}, [%4];"
                 : "=r"(r[0]), "=r"(r[1]), "=r"(r[2]), "=r"(r[3]) : "r"(addr));
}
__device__ __forceinline__ void mma16816(float* c, const uint32_t* a, uint32_t b0, uint32_t b1) {
    asm volatile(
        "mma.sync.aligned.m16n8k16.row.col.f32.bf16.bf16.f32 "
        "{%0,%1,%2,%3}, {%4,%5,%6,%7}, {%8,%9}, {%0,%1,%2,%3};"
        : "+f"(c[0]), "+f"(c[1]), "+f"(c[2]), "+f"(c[3])
        : "r"(a[0]), "r"(a[1]), "r"(a[2]), "r"(a[3]), "r"(b0), "r"(b1));
}
__device__ __forceinline__ void cp16(uint32_t s, const void* g) {
    asm volatile("cp.async.cg.shared.global [%0], [%1], 16;\n" :: "r"(s), "l"(g));
}

// ---------------- fused weight convert: all 33 weights in ONE launch ----------------
struct ConvEnt {
    const float* W;
    long long off;            // element offset into g_WH / g_WL
    int K, N, kpad, tiles_n, tileStart;
};
struct ConvTab { ConvEnt e[33]; int cnt; };

__global__ void convw_all_kernel(ConvTab tab, __nv_bfloat16* __restrict__ WH,
                                 __nv_bfloat16* __restrict__ WL) {
    __shared__ float t[32][33];
    int b = blockIdx.x;
    int i = 0;
    #pragma unroll 1
    while (i + 1 < tab.cnt && tab.e[i + 1].tileStart <= b) i++;
    const ConvEnt en = tab.e[i];
    int local = b - en.tileStart;
    int nb = (local % en.tiles_n) * 32;
    int kb = (local / en.tiles_n) * 32;
    __nv_bfloat16* TH = WH + en.off;
    __nv_bfloat16* TL = WL + en.off;

    int tid = threadIdx.x;
    int tx = tid & 31, ty = tid >> 5;
    #pragma unroll
    for (int r = 0; r < 4; r++) {
        int k = kb + ty + 8 * r, n = nb + tx;
        t[ty + 8 * r][tx] = (k < en.K && n < en.N) ? en.W[(size_t)k * en.N + n] : 0.f;
    }
    __syncthreads();
    int nrow = tid >> 3, kp = tid & 7;
    #pragma unroll
    for (int w = 0; w < 2; w++) {
        int kk = (kp + 8 * w) * 2;
        float f0 = t[kk][nrow], f1 = t[kk + 1][nrow];
        uint32_t hi, lo;
        split2(f0, f1, hi, lo);
        size_t o = (size_t)(nb + nrow) * en.kpad + kb + kk;
        *(uint32_t*)&TH[o] = hi;
        *(uint32_t*)&TL[o] = lo;
    }
}

// ---------------- tensor-core GEMM: C[M,N] = A @ B^T (+C), bf16 hi/lo inputs ----------
// 128x128 CTA tile, BK=64, 3-stage cp.async ring (3 x 64KB), 8 warps, 3-term split MMA.
__global__ __launch_bounds__(256, 1)
void gemm_bf16_kernel(const __nv_bfloat16* __restrict__ AH, const __nv_bfloat16* __restrict__ AL,
                      const __nv_bfloat16* __restrict__ BH, const __nv_bfloat16* __restrict__ BL,
                      float* __restrict__ C, int M, int N, int lda, int ldb,
                      int ktiles, int addC) {
    extern __shared__ char smraw[];
    uint32_t sbase = smem_u32(smraw);
    int tid = threadIdx.x, warp = tid >> 5, lane = tid & 31;
    int wm = (warp >> 1) * 32, wn = (warp & 1) * 64;
    int m0 = blockIdx.y * 128, n0 = blockIdx.x * 128;

    float acc[2][8][4];
    #pragma unroll
    for (int mi = 0; mi < 2; mi++)
        #pragma unroll
        for (int ni = 0; ni < 8; ni++)
            acc[mi][ni][0] = acc[mi][ni][1] = acc[mi][ni][2] = acc[mi][ni][3] = 0.f;

    int srow = tid >> 3, skc = tid & 7;

    auto stage = [&](int t, int buf) {
        int k0 = t << 6;
        uint32_t sb = sbase + (uint32_t)buf * 65536u;
        #pragma unroll
        for (int i = 0; i < 4; i++) {
            int row = srow + i * 32;
            uint32_t soff = (uint32_t)row * 128 + (uint32_t)((skc ^ (row & 7)) << 4);
            size_t ao = (size_t)(m0 + row) * lda + k0 + skc * 8;
            size_t bo = (size_t)(n0 + row) * ldb + k0 + skc * 8;
            cp16(sb + soff,          AH + ao);
            cp16(sb + 16384 + soff,  AL + ao);
            cp16(sb + 32768 + soff,  BH + bo);
            cp16(sb + 49152 + soff,  BL + bo);
        }
        asm volatile("cp.async.commit_group;\n" ::: "memory");
    };

    stage(0, 0);
    if (ktiles > 1) stage(1, 1);
    int bt = 0;
    for (int t = 0; t < ktiles; t++) {
        asm volatile("cp.async.wait_group 1;\n" ::: "memory");   // tile t resident
        __syncthreads();                                          // + all warps done with buf (t-1)%3
        if (t + 2 < ktiles) {
            int nb = bt + 2;
            if (nb >= 3) nb -= 3;                                 // tile t+2 -> buffer (t+2)%3
            stage(t + 2, nb);
        }

        uint32_t aHb = sbase + (uint32_t)bt * 65536u;
        uint32_t aLb = aHb + 16384, bHb = aHb + 32768, bLb = aHb + 49152;
        #pragma unroll
        for (int ks = 0; ks < 4; ks++) {
            uint32_t ah[2][4], al[2][4];
            #pragma unroll
            for (int mi = 0; mi < 2; mi++) {
                int row = wm + mi * 16 + (lane & 15);
                int c = ks * 2 + (lane >> 4);
                uint32_t off = (uint32_t)row * 128 + (uint32_t)((c ^ (row & 7)) << 4);
                ldsm4(ah[mi], aHb + off);
                ldsm4(al[mi], aLb + off);
            }
            #pragma unroll
            for (int np = 0; np < 4; np++) {
                uint32_t bh[4], bl[4];
                int row = wn + np * 16 + (lane & 15);
                int c = ks * 2 + (lane >> 4);
                uint32_t off = (uint32_t)row * 128 + (uint32_t)((c ^ (row & 7)) << 4);
                ldsm4(bh, bHb + off);
                ldsm4(bl, bLb + off);
                #pragma unroll
                for (int mi = 0; mi < 2; mi++) {
                    mma16816(acc[mi][2 * np],     ah[mi], bh[0], bh[2]);
                    mma16816(acc[mi][2 * np],     al[mi], bh[0], bh[2]);
                    mma16816(acc[mi][2 * np],     ah[mi], bl[0], bl[2]);
                    mma16816(acc[mi][2 * np + 1], ah[mi], bh[1], bh[3]);
                    mma16816(acc[mi][2 * np + 1], al[mi], bh[1], bh[3]);
                    mma16816(acc[mi][2 * np + 1], ah[mi], bl[1], bl[3]);
                }
            }
        }
        bt = (bt + 1 == 3) ? 0 : bt + 1;
    }

    // ---- epilogue ----
    int gid = lane >> 2, tig = lane & 3;
    #pragma unroll
    for (int mi = 0; mi < 2; mi++) {
        #pragma unroll
        for (int ni = 0; ni < 8; ni++) {
            int row = m0 + wm + mi * 16 + gid;
            int col = n0 + wn + ni * 8 + tig * 2;
            if (col + 1 < N && row < M) {
                float* cp = &C[(size_t)row * N + col];
                float2 v = make_float2(acc[mi][ni][0], acc[mi][ni][1]);
                if (addC) { float2 o = *(float2*)cp; v.x += o.x; v.y += o.y; }
                *(float2*)cp = v;
                float* cp8 = cp + 8 * (size_t)N;
                float2 w = make_float2(acc[mi][ni][2], acc[mi][ni][3]);
                if (addC) { float2 o = *(float2*)cp8; w.x += o.x; w.y += o.y; }
                *(float2*)cp8 = w;
            }
        }
    }
}

// ---------------- embeddings ----------------
__global__ void embed_img_kernel(const int* __restrict__ ids, const float* __restrict__ te,
                                 const float* __restrict__ pe, float* __restrict__ out) {
    int i = blockIdx.x * blockDim.x + threadIdx.x;
    if (i >= NTOK * DMODEL) return;
    int n = i >> 10, d = i & 1023;
    out[i] = te[(size_t)ids[n] * DMODEL + d] + pe[i];
}
__global__ void embed_ctx_kernel(const int* __restrict__ ids, const float* __restrict__ te,
                                 const float* __restrict__ pe,
                                 __nv_bfloat16* __restrict__ Yh, __nv_bfloat16* __restrict__ Yl) {
    int p = blockIdx.x * blockDim.x + threadIdx.x;
    if (p >= NCTX * DMODEL / 2) return;
    int i = p * 2;
    int n = i >> 10, d = i & 1023;
    const float* row = te + (size_t)ids[n] * DMODEL;
    float f0 = row[d] + pe[i];
    float f1 = row[d + 1] + pe[i + 1];
    uint32_t hi, lo;
    split2(f0, f1, hi, lo);
    *(uint32_t*)&Yh[i] = hi;
    *(uint32_t*)&Yl[i] = lo;
}

// ---------------- LayerNorm -> bf16 hi/lo (C = 1024 fixed) ----------------
__global__ void ln_kernel(const float* __restrict__ X, const float* __restrict__ g,
                          __nv_bfloat16* __restrict__ Yh, __nv_bfloat16* __restrict__ Yl) {
    int row = blockIdx.x;
    const float* x = X + (size_t)row * DMODEL;
    int tid = threadIdx.x;
    float v[4], s1 = 0.f, s2 = 0.f;
    #pragma unroll
    for (int j = 0; j < 4; j++) { v[j] = x[tid * 4 + j]; s1 += v[j]; s2 += v[j] * v[j]; }
    __shared__ float red[512];
    red[tid] = s1; red[256 + tid] = s2;
    __syncthreads();
    for (int s = 128; s > 0; s >>= 1) {
        if (tid < s) { red[tid] += red[tid + s]; red[256 + tid] += red[256 + tid + s]; }
        __syncthreads();
    }
    float mean = red[0] / DMODEL;
    float var  = red[256] / DMODEL - mean * mean;
    float inv  = rsqrtf(var + 1e-5f);
    float y[4];
    #pragma unroll
    for (int j = 0; j < 4; j++) y[j] = (v[j] - mean) * inv * g[tid * 4 + j];
    uint32_t h0, l0, h1, l1;
    split2(y[0], y[1], h0, l0);
    split2(y[2], y[3], h1, l1);
    size_t o = (size_t)row * DMODEL + tid * 4;
    *(uint2*)&Yh[o] = make_uint2(h0, h1);
    *(uint2*)&Yl[o] = make_uint2(l0, l1);
}

// ---------------- fused GEGLU + LayerNorm -> bf16 hi/lo [row][FFIP] ----------------
__global__ void geglu_ln_kernel(const float* __restrict__ HH, const float* __restrict__ g2,
                                __nv_bfloat16* __restrict__ Yh, __nv_bfloat16* __restrict__ Yl) {
    int row = blockIdx.x;
    const float* h = HH + (size_t)row * FF2;
    int tid = threadIdx.x;
    __shared__ float buf[FFI];
    __shared__ float red[512];
    float s1 = 0.f, s2 = 0.f;
    for (int c = tid; c < FFI; c += 256) {
        float a = h[c], gate = h[FFI + c];
        float v = gate * (0.5f * a * (1.0f + erff(a * 0.70710678118654752f)));
        buf[c] = v; s1 += v; s2 += v * v;
    }
    red[tid] = s1; red[256 + tid] = s2;
    __syncthreads();
    for (int s = 128; s > 0; s >>= 1) {
        if (tid < s) { red[tid] += red[tid + s]; red[256 + tid] += red[256 + tid + s]; }
        __syncthreads();
    }
    float mean = red[0] / FFI;
    float var  = red[256] / FFI - mean * mean;
    float inv  = rsqrtf(var + 1e-5f);
    for (int q = tid; q < FFIP / 4; q += 256) {
        int c = q * 4;
        float y[4];
        #pragma unroll
        for (int j = 0; j < 4; j++) {
            int cc = c + j;
            y[j] = (cc < FFI) ? (buf[cc] - mean) * inv * g2[cc] : 0.f;
        }
        uint32_t h0, l0, h1, l1;
        split2(y[0], y[1], h0, l0);
        split2(y[2], y[3], h1, l1);
        size_t o = (size_t)row * FFIP + c;
        *(uint2*)&Yh[o] = make_uint2(h0, h1);
        *(uint2*)&Yl[o] = make_uint2(l0, l1);
    }
}

// ---------------- Q prep ----------------
__global__ void prep_q_kernel(const float* __restrict__ Qin, const float* __restrict__ qs,
                              float* __restrict__ QN, int Nq) {
    int gw = (blockIdx.x * blockDim.x + threadIdx.x) >> 5;
    int lane = threadIdx.x & 31;
    if (gw >= NHEAD * Nq) return;
    int h = gw / Nq, n = gw % Nq;
    const float* src = Qin + (size_t)n * DMODEL + h * DHEAD;
    float v0 = src[lane], v1 = src[lane + 32];
    float ss = v0 * v0 + v1 * v1;
    #pragma unroll
    for (int s = 16; s; s >>= 1) ss += __shfl_xor_sync(0xffffffffu, ss, s);
    float inv = 1.0f / fmaxf(sqrtf(ss), 1e-12f);
    float* dst = QN + ((size_t)h * Nq + n) * DHEAD;
    dst[lane]      = v0 * inv * qs[lane] * 8.0f;
    dst[lane + 32] = v1 * inv * qs[lane + 32] * 8.0f;
}

// ---------------- KV prep ----------------
__global__ void prep_kv_kernel(const float* __restrict__ KVin, const float* __restrict__ nullp,
                               const float* __restrict__ ks, float* __restrict__ Ko,
                               float* __restrict__ Vo, int Nt) {
    int NK = Nt + 1;
    int gw = (blockIdx.x * blockDim.x + threadIdx.x) >> 5;
    int lane = threadIdx.x & 31;
    if (gw >= NHEAD * NK) return;
    int h = gw / NK, j = gw % NK;
    float k0, k1, v0, v1;
    if (j == 0) {
        k0 = nullp[h * DHEAD + lane];
        k1 = nullp[h * DHEAD + lane + 32];
        v0 = nullp[NHEAD * DHEAD + h * DHEAD + lane];
        v1 = nullp[NHEAD * DHEAD + h * DHEAD + lane + 32];
    } else {
        const float* src = KVin + (size_t)(j - 1) * (2 * DMODEL) + h * DHEAD;
        k0 = src[lane];          k1 = src[lane + 32];
        v0 = src[DMODEL + lane]; v1 = src[DMODEL + lane + 32];
    }
    float ss = k0 * k0 + k1 * k1;
    #pragma unroll
    for (int s = 16; s; s >>= 1) ss += __shfl_xor_sync(0xffffffffu, ss, s);
    float inv = 1.0f / fmaxf(sqrtf(ss), 1e-12f);
    size_t base = ((size_t)h * NK + j) * DHEAD;
    Ko[base + lane]      = k0 * inv * ks[lane];
    Ko[base + lane + 32] = k1 * inv * ks[lane + 32];
    Vo[base + lane]      = v0;
    Vo[base + lane + 32] = v1;
}

// ---------------- fused flash attention (scalar; epilogue emits bf16 hi/lo) ----------------
__global__ __launch_bounds__(256, 2)
void flash_kernel(const float* __restrict__ Q, const float* __restrict__ K,
                  const float* __restrict__ V,
                  __nv_bfloat16* __restrict__ Oh, __nv_bfloat16* __restrict__ Ol,
                  int Nq, int NK) {
    extern __shared__ float sm[];
    float* Qs = sm;
    float* KT = sm + 8192;
    float* Ps = sm + 12288;
    int h  = blockIdx.y;
    int qb = blockIdx.x * 128;
    int tid = threadIdx.x;
    int tx = tid & 15, ty = tid >> 4;
    int r0 = ty * 8, c0 = tx * 4;

    const float* Qg = Q + ((size_t)h * Nq + qb) * DHEAD;
    for (int i = tid * 4; i < 8192; i += 1024)
        *(float4*)&Qs[i] = *(const float4*)&Qg[i];

    float o[8][4];
    float mrow[8], lrow[8];
    #pragma unroll
    for (int i = 0; i < 8; i++) {
        mrow[i] = -1e30f; lrow[i] = 0.f;
        o[i][0] = o[i][1] = o[i][2] = o[i][3] = 0.f;
    }

    int ntiles = (NK + 63) >> 6;
    int kj = tid & 63, kd = (tid >> 6) << 4;

    for (int t = 0; t < ntiles; t++) {
        int kb = t << 6;
        __syncthreads();
        {
            bool valid = (kb + kj) < NK;
            const float* Kg = K + ((size_t)h * NK + kb + kj) * DHEAD;
            #pragma unroll
            for (int r = 0; r < 4; r++) {
                int d0 = kd + r * 4;
                float4 g = valid ? *(const float4*)&Kg[d0] : make_float4(0, 0, 0, 0);
                KT[(d0 + 0) * 64 + kj] = g.x;
                KT[(d0 + 1) * 64 + kj] = g.y;
                KT[(d0 + 2) * 64 + kj] = g.z;
                KT[(d0 + 3) * 64 + kj] = g.w;
            }
        }
        __syncthreads();

        float acc[8][4];
        #pragma unroll
        for (int i = 0; i < 8; i++) acc[i][0] = acc[i][1] = acc[i][2] = acc[i][3] = 0.f;
        #pragma unroll
        for (int d = 0; d < 64; d += 4) {
            float4 k4[4];
            #pragma unroll
            for (int j = 0; j < 4; j++) k4[j] = *(float4*)&KT[(d + j) * 64 + c0];
            #pragma unroll
            for (int i = 0; i < 8; i++) {
                float4 q4 = *(float4*)&Qs[(r0 + i) * 64 + d];
                acc[i][0] += q4.x * k4[0].x + q4.y * k4[1].x + q4.z * k4[2].x + q4.w * k4[3].x;
                acc[i][1] += q4.x * k4[0].y + q4.y * k4[1].y + q4.z * k4[2].y + q4.w * k4[3].y;
                acc[i][2] += q4.x * k4[0].z + q4.y * k4[1].z + q4.z * k4[2].z + q4.w * k4[3].z;
                acc[i][3] += q4.x * k4[0].w + q4.y * k4[1].w + q4.z * k4[2].w + q4.w * k4[3].w;
            }
        }
        if (kb + 64 > NK) {
            #pragma unroll
            for (int j = 0; j < 4; j++)
                if (kb + c0 + j >= NK)
                    #pragma unroll
                    for (int i = 0; i < 8; i++) acc[i][j] = -1e30f;
        }
        float tmax[8];
        #pragma unroll
        for (int i = 0; i < 8; i++)
            tmax[i] = fmaxf(fmaxf(acc[i][0], acc[i][1]), fmaxf(acc[i][2], acc[i][3]));
        #pragma unroll
        for (int s = 1; s < 16; s <<= 1)
            #pragma unroll
            for (int i = 0; i < 8; i++)
                tmax[i] = fmaxf(tmax[i], __shfl_xor_sync(0xffffffffu, tmax[i], s, 32));
        float corr[8];
        #pragma unroll
        for (int i = 0; i < 8; i++) {
            float mnew = fmaxf(mrow[i], tmax[i]);
            corr[i] = expf(mrow[i] - mnew);
            mrow[i] = mnew;
        }
        float rsum[8];
        #pragma unroll
        for (int i = 0; i < 8; i++) {
            float s = 0.f;
            #pragma unroll
            for (int j = 0; j < 4; j++) {
                float p = expf(acc[i][j] - mrow[i]);
                acc[i][j] = p; s += p;
            }
            rsum[i] = s;
        }
        #pragma unroll
        for (int s = 1; s < 16; s <<= 1)
            #pragma unroll
            for (int i = 0; i < 8; i++)
                rsum[i] += __shfl_xor_sync(0xffffffffu, rsum[i], s, 32);
        #pragma unroll
        for (int i = 0; i < 8; i++) {
            lrow[i] = lrow[i] * corr[i] + rsum[i];
            o[i][0] *= corr[i]; o[i][1] *= corr[i]; o[i][2] *= corr[i]; o[i][3] *= corr[i];
            *(float4*)&Ps[(r0 + i) * 64 + c0] = make_float4(acc[i][0], acc[i][1], acc[i][2], acc[i][3]);
        }
        __syncthreads();
        for (int i = tid * 4; i < 4096; i += 1024) {
            int j = i >> 6;
            *(float4*)&KT[i] = (kb + j < NK)
                ? *(const float4*)&V[((size_t)h * NK + kb + j) * DHEAD + (i & 63)]
                : make_float4(0, 0, 0, 0);
        }
        __syncthreads();
        #pragma unroll
        for (int jk = 0; jk < 64; jk += 4) {
            float4 v4[4];
            #pragma unroll
            for (int jj = 0; jj < 4; jj++) v4[jj] = *(float4*)&KT[(jk + jj) * 64 + c0];
            #pragma unroll
            for (int i = 0; i < 8; i++) {
                float4 p4 = *(float4*)&Ps[(r0 + i) * 64 + jk];
                o[i][0] += p4.x * v4[0].x + p4.y * v4[1].x + p4.z * v4[2].x + p4.w * v4[3].x;
                o[i][1] += p4.x * v4[0].y + p4.y * v4[1].y + p4.z * v4[2].y + p4.w * v4[3].y;
                o[i][2] += p4.x * v4[0].z + p4.y * v4[1].z + p4.z * v4[2].z + p4.w * v4[3].z;
                o[i][3] += p4.x * v4[0].w + p4.y * v4[1].w + p4.z * v4[2].w + p4.w * v4[3].w;
            }
        }
    }
    #pragma unroll
    for (int i = 0; i < 8; i++) {
        float inv = 1.f / lrow[i];
        int n = qb + r0 + i;
        uint32_t h0, l0, h1, l1;
        split2(o[i][0] * inv, o[i][1] * inv, h0, l0);
        split2(o[i][2] * inv, o[i][3] * inv, h1, l1);
        size_t off = (size_t)n * DMODEL + h * DHEAD + c0;
        *(uint2*)&Oh[off] = make_uint2(h0, h1);
        *(uint2*)&Ol[off] = make_uint2(l0, l1);
    }
}

// ---------------- host orchestration ----------------
extern "C" void kernel_launch(void* const* d_in, const int* in_sizes, int n_in,
                              void* d_out, int out_size) {
    (void)in_sizes; (void)n_in; (void)out_size;
    const int*   x_ids    = (const int*)d_in[0];
    const int*   cond_ids = (const int*)d_in[1];
    const float* token_emb = (const float*)d_in[2];
    const float* pos_emb   = (const float*)d_in[3];
    const float* cte       = (const float*)d_in[4];
    const float* cpe       = (const float*)d_in[5];
    const float* sa_g    = (const float*)d_in[6];
    const float* sa_wq   = (const float*)d_in[7];
    const float* sa_wkv  = (const float*)d_in[8];
    const float* sa_null = (const float*)d_in[9];
    const float* sa_qs   = (const float*)d_in[10];
    const float* sa_ks   = (const float*)d_in[11];
    const float* sa_wo   = (const float*)d_in[12];
    const float* ca_g    = (const float*)d_in[13];
    const float* ca_wq   = (const float*)d_in[14];
    const float* ca_wkv  = (const float*)d_in[15];
    const float* ca_null = (const float*)d_in[16];
    const float* ca_qs   = (const float*)d_in[17];
    const float* ca_ks   = (const float*)d_in[18];
    const float* ca_wo   = (const float*)d_in[19];
    const float* ff_g1   = (const float*)d_in[20];
    const float* ff_w1   = (const float*)d_in[21];
    const float* ff_g2   = (const float*)d_in[22];
    const float* ff_w2   = (const float*)d_in[23];
    const float* final_g  = (const float*)d_in[24];
    const float* w_logits = (const float*)d_in[25];
    float* out = (float*)d_out;

    float *H, *Q, *KV, *QN, *K, *V, *HH;
    __nv_bfloat16 *WH, *WL, *XNh, *XNl, *CTXh, *CTXl, *Oh, *Ol, *GNh, *GNl;
    cudaGetSymbolAddress((void**)&H,   g_H);
    cudaGetSymbolAddress((void**)&Q,   g_Q);
    cudaGetSymbolAddress((void**)&KV,  g_KV);
    cudaGetSymbolAddress((void**)&QN,  g_QN);
    cudaGetSymbolAddress((void**)&K,   g_K);
    cudaGetSymbolAddress((void**)&V,   g_V);
    cudaGetSymbolAddress((void**)&HH,  g_HH);
    cudaGetSymbolAddress((void**)&WH,  g_WH);
    cudaGetSymbolAddress((void**)&WL,  g_WL);
    cudaGetSymbolAddress((void**)&XNh, g_XNh);
    cudaGetSymbolAddress((void**)&XNl, g_XNl);
    cudaGetSymbolAddress((void**)&CTXh, g_CTXh);
    cudaGetSymbolAddress((void**)&CTXl, g_CTXl);
    cudaGetSymbolAddress((void**)&Oh,  g_Oh);
    cudaGetSymbolAddress((void**)&Ol,  g_Ol);
    cudaGetSymbolAddress((void**)&GNh, g_GNh);
    cudaGetSymbolAddress((void**)&GNl, g_GNl);

    const int FLASH_SMEM = 20480 * 4;    // 80KB
    const int GEMM_SMEM  = 196608;       // 192KB (3 x 64KB ring)
    cudaFuncSetAttribute(flash_kernel, cudaFuncAttributeMaxDynamicSharedMemorySize, FLASH_SMEM);
    cudaFuncSetAttribute(gemm_bf16_kernel, cudaFuncAttributeMaxDynamicSharedMemorySize, GEMM_SMEM);

    // ---- fused weight conversion: one launch for all 33 weights ----
    {
        ConvTab tab;
        int cnt = 0, tiles = 0;
        auto add = [&](const float* W, long long off, int Kd, int Nd, int k_pad, int n_pad) {
            ConvEnt& e = tab.e[cnt++];
            e.W = W; e.off = off; e.K = Kd; e.N = Nd; e.kpad = k_pad;
            e.tiles_n = n_pad / 32; e.tileStart = tiles;
            tiles += (n_pad / 32) * (k_pad / 32);
        };
        for (int l = 0; l < NLAYER; l++) {
            long long lb = (long long)l * LBLK;
            add(sa_wq  + (size_t)l * DMODEL * DMODEL,     lb + W_WQ,   1024, 1024, 1024, 1024);
            add(sa_wkv + (size_t)l * DMODEL * 2 * DMODEL, lb + W_WKV,  1024, 2048, 1024, 2048);
            add(sa_wo  + (size_t)l * DMODEL * DMODEL,     lb + W_WO,   1024, 1024, 1024, 1024);
            add(ca_wq  + (size_t)l * DMODEL * DMODEL,     lb + W_CWQ,  1024, 1024, 1024, 1024);
            add(ca_wkv + (size_t)l * DMODEL * 2 * DMODEL, lb + W_CWKV, 1024, 2048, 1024, 2048);
            add(ca_wo  + (size_t)l * DMODEL * DMODEL,     lb + W_CWO,  1024, 1024, 1024, 1024);
            add(ff_w1  + (size_t)l * DMODEL * FF2,        lb + W_FF1,  1024, FF2,  1024, 5504);
            add(ff_w2  + (size_t)l * FFI * DMODEL,        lb + W_FF2,  FFI,  1024, FFIP, 1024);
        }
        add(w_logits, W_LOG, 1024, VOCAB, 1024, VOCAB);
        tab.cnt = cnt;
        convw_all_kernel<<<tiles, 256>>>(tab, WH, WL);
    }

    embed_img_kernel<<<(NTOK * DMODEL) / 256, 256>>>(x_ids, token_emb, pos_emb, H);
    embed_ctx_kernel<<<(NCTX * DMODEL / 2) / 256, 256>>>(cond_ids, cte, cpe, CTXh, CTXl);

    auto gemm = [&](const __nv_bfloat16* aH, const __nv_bfloat16* aL, size_t woff,
                    float* Cp, int M, int N, int lda, int ldb, int ktiles, int addC,
                    int gx, int gy) {
        gemm_bf16_kernel<<<dim3(gx, gy), 256, GEMM_SMEM>>>(aH, aL, WH + woff, WL + woff,
                                                           Cp, M, N, lda, ldb, ktiles, addC);
    };

    for (int l = 0; l < NLAYER; l++) {
        size_t lb = (size_t)l * LBLK;
        // ------- self attention -------
        ln_kernel<<<NTOK, 256>>>(H, sa_g + (size_t)l * DMODEL, XNh, XNl);
        gemm(XNh, XNl, lb + W_WQ,  Q,  NTOK, 1024, 1024, 1024, 16, 0, 8, 12);
        gemm(XNh, XNl, lb + W_WKV, KV, NTOK, 2048, 1024, 1024, 16, 0, 16, 12);
        prep_q_kernel<<<(NHEAD * NTOK + 7) / 8, 256>>>(Q, sa_qs + l * DHEAD, QN, NTOK);
        prep_kv_kernel<<<(NHEAD * (NTOK + 1) + 7) / 8, 256>>>(KV, sa_null + (size_t)l * 2 * NHEAD * DHEAD,
                                                              sa_ks + l * DHEAD, K, V, NTOK);
        flash_kernel<<<dim3(NTOK / 128, NHEAD), 256, FLASH_SMEM>>>(QN, K, V, Oh, Ol, NTOK, NTOK + 1);
        gemm(Oh, Ol, lb + W_WO, H, NTOK, 1024, 1024, 1024, 16, 1, 8, 12);

        // ------- cross attention -------
        ln_kernel<<<NTOK, 256>>>(H, ca_g + (size_t)l * DMODEL, XNh, XNl);
        gemm(XNh, XNl, lb + W_CWQ, Q, NTOK, 1024, 1024, 1024, 16, 0, 8, 12);
        gemm(CTXh, CTXl, lb + W_CWKV, KV, NCTX, 2048, 1024, 1024, 16, 0, 16, 4);
        prep_q_kernel<<<(NHEAD * NTOK + 7) / 8, 256>>>(Q, ca_qs + l * DHEAD, QN, NTOK);
        prep_kv_kernel<<<(NHEAD * (NCTX + 1) + 7) / 8, 256>>>(KV, ca_null + (size_t)l * 2 * NHEAD * DHEAD,
                                                              ca_ks + l * DHEAD, K, V, NCTX);
        flash_kernel<<<dim3(NTOK / 128, NHEAD), 256, FLASH_SMEM>>>(QN, K, V, Oh, Ol, NTOK, NCTX + 1);
        gemm(Oh, Ol, lb + W_CWO, H, NTOK, 1024, 1024, 1024, 16, 1, 8, 12);

        // ------- GEGLU feedforward -------
        ln_kernel<<<NTOK, 256>>>(H, ff_g1 + (size_t)l * DMODEL, XNh, XNl);
        gemm(XNh, XNl, lb + W_FF1, HH, NTOK, FF2, 1024, 1024, 16, 0, 43, 12);
        geglu_ln_kernel<<<NTOK, 256>>>(HH, ff_g2 + (size_t)l * FFI, GNh, GNl);
        gemm(GNh, GNl, lb + W_FF2, H, NTOK, 1024, FFIP, FFIP, 43, 1, 8, 12);
    }

    // ------- final norm + logits -------
    ln_kernel<<<NTOK, 256>>>(H, final_g, XNh, XNl);
    gemm(XNh, XNl, W_LOG, out, NTOK, VOCAB, 1024, 1024, 16, 0, 64, 12);
}

// round 11
// speedup vs baseline: 2.5685x; 1.0469x over previous
#include <cuda_runtime.h>
#include <cuda_bf16.h>
#include <math.h>
#include <stdint.h>

// ---------------- model dims ----------------
#define NLAYER 4
#define DMODEL 1024
#define NHEAD  16
#define DHEAD  64
#define NTOK   1536
#define NCTX   512
#define VOCAB  8192
#define FFI    2730          // GEGLU inner
#define FF2    5460          // 2*FFI
#define FFIP   2752          // FFI padded to 64

// ---------------- weight scratch offsets (padded, transposed [n][k] bf16) ----------------
// W_WQ and W_WKV are contiguous with the same kpad=1024 -> fused QKV GEMM reads both.
#define W_WQ    0ull
#define W_WKV   1048576ull
#define W_WO    3145728ull
#define W_CWQ   4194304ull
#define W_CWKV  5242880ull
#define W_CWO   7340032ull
#define W_FF1   8388608ull
#define W_FF2   14024704ull
#define LBLK    16842752ull
#define W_LOG   67371008ull
#define WTOT    75759616ull

// ---------------- scratch (device globals; no allocation allowed) ----------------
__device__ float g_H  [NTOK * DMODEL];
__device__ float g_QKV[NTOK * 3 * DMODEL];      // fused self-attn Q|K|V
__device__ float g_Q  [NTOK * DMODEL];          // cross-attn Q
__device__ float g_KV [NCTX * 2 * DMODEL];      // cross-attn KV
__device__ float g_QN [NHEAD * NTOK * DHEAD];
__device__ float g_K  [NHEAD * (NTOK + 1) * DHEAD];
__device__ float g_V  [NHEAD * (NTOK + 1) * DHEAD];
__device__ float g_HH [NTOK * FF2];

__device__ __align__(128) __nv_bfloat16 g_WH[WTOT];
__device__ __align__(128) __nv_bfloat16 g_WL[WTOT];
__device__ __align__(128) __nv_bfloat16 g_XNh[NTOK * DMODEL],  g_XNl[NTOK * DMODEL];
__device__ __align__(128) __nv_bfloat16 g_CTXh[NCTX * DMODEL], g_CTXl[NCTX * DMODEL];
__device__ __align__(128) __nv_bfloat16 g_Oh[NTOK * DMODEL],   g_Ol[NTOK * DMODEL];
__device__ __align__(128) __nv_bfloat16 g_GNh[NTOK * FFIP],    g_GNl[NTOK * FFIP];

// ---------------- helpers ----------------
__device__ __forceinline__ uint32_t smem_u32(const void* p) {
    uint32_t a;
    asm("{ .reg .u64 t; cvta.to.shared.u64 t, %1; cvt.u32.u64 %0, t; }" : "=r"(a) : "l"(p));
    return a;
}
__device__ __forceinline__ void split2(float f0, float f1, uint32_t& hi, uint32_t& lo) {
    __nv_bfloat16 h0 = __float2bfloat16(f0), h1 = __float2bfloat16(f1);
    float r0 = f0 - __bfloat162float(h0), r1 = f1 - __bfloat162float(h1);
    __nv_bfloat16 l0 = __float2bfloat16(r0), l1 = __float2bfloat16(r1);
    hi = (uint32_t)__bfloat16_as_ushort(h0) | ((uint32_t)__bfloat16_as_ushort(h1) << 16);
    lo = (uint32_t)__bfloat16_as_ushort(l0) | ((uint32_t)__bfloat16_as_ushort(l1) << 16);
}
__device__ __forceinline__ void ldsm4(uint32_t* r, uint32_t addr) {
    asm volatile("ldmatrix.sync.aligned.m8n8.x4.shared.b16 {%0,%1,%2,%3}, [%4];"
                 : "=r"(r[0]), "=r"(r[1]), "=r"(r[2]), "=r"(r[3]) : "r"(addr));
}
__device__ __forceinline__ void mma16816(float* c, const uint32_t* a, uint32_t b0, uint32_t b1) {
    asm volatile(
        "mma.sync.aligned.m16n8k16.row.col.f32.bf16.bf16.f32 "
        "{%0,%1,%2,%3}, {%4,%5,%6,%7}, {%8,%9}, {%0,%1,%2,%3};"
        : "+f"(c[0]), "+f"(c[1]), "+f"(c[2]), "+f"(c[3])
        : "r"(a[0]), "r"(a[1]), "r"(a[2]), "r"(a[3]), "r"(b0), "r"(b1));
}
__device__ __forceinline__ void cp16(uint32_t s, const void* g) {
    asm volatile("cp.async.cg.shared.global [%0], [%1], 16;\n" :: "r"(s), "l"(g));
}

// ---------------- fused weight convert: all 33 weights in ONE launch ----------------
struct ConvEnt {
    const float* W;
    long long off;
    int K, N, kpad, tiles_n, tileStart;
};
struct ConvTab { ConvEnt e[33]; int cnt; };

__global__ void convw_all_kernel(ConvTab tab, __nv_bfloat16* __restrict__ WH,
                                 __nv_bfloat16* __restrict__ WL) {
    __shared__ float t[32][33];
    int b = blockIdx.x;
    int i = 0;
    #pragma unroll 1
    while (i + 1 < tab.cnt && tab.e[i + 1].tileStart <= b) i++;
    const ConvEnt en = tab.e[i];
    int local = b - en.tileStart;
    int nb = (local % en.tiles_n) * 32;
    int kb = (local / en.tiles_n) * 32;
    __nv_bfloat16* TH = WH + en.off;
    __nv_bfloat16* TL = WL + en.off;

    int tid = threadIdx.x;
    int tx = tid & 31, ty = tid >> 5;
    #pragma unroll
    for (int r = 0; r < 4; r++) {
        int k = kb + ty + 8 * r, n = nb + tx;
        t[ty + 8 * r][tx] = (k < en.K && n < en.N) ? en.W[(size_t)k * en.N + n] : 0.f;
    }
    __syncthreads();
    int nrow = tid >> 3, kp = tid & 7;
    #pragma unroll
    for (int w = 0; w < 2; w++) {
        int kk = (kp + 8 * w) * 2;
        float f0 = t[kk][nrow], f1 = t[kk + 1][nrow];
        uint32_t hi, lo;
        split2(f0, f1, hi, lo);
        size_t o = (size_t)(nb + nrow) * en.kpad + kb + kk;
        *(uint32_t*)&TH[o] = hi;
        *(uint32_t*)&TL[o] = lo;
    }
}

// ---------------- tensor-core GEMM: C[M,N] = A @ B^T (+C), bf16 hi/lo inputs ----------
// 128x128 CTA tile, BK=64, 3-stage cp.async ring, 512 threads / 16 warps (32x32 warp
// tile -> 4 warps per SMSP for latency hiding), 3-term split MMA.
__global__ __launch_bounds__(512, 1)
void gemm_bf16_kernel(const __nv_bfloat16* __restrict__ AH, const __nv_bfloat16* __restrict__ AL,
                      const __nv_bfloat16* __restrict__ BH, const __nv_bfloat16* __restrict__ BL,
                      float* __restrict__ C, int M, int N, int lda, int ldb,
                      int ktiles, int addC) {
    extern __shared__ char smraw[];
    uint32_t sbase = smem_u32(smraw);
    int tid = threadIdx.x, warp = tid >> 5, lane = tid & 31;
    int wm = (warp >> 2) * 32, wn = (warp & 3) * 32;
    int m0 = blockIdx.y * 128, n0 = blockIdx.x * 128;

    float acc[2][4][4];
    #pragma unroll
    for (int mi = 0; mi < 2; mi++)
        #pragma unroll
        for (int ni = 0; ni < 4; ni++)
            acc[mi][ni][0] = acc[mi][ni][1] = acc[mi][ni][2] = acc[mi][ni][3] = 0.f;

    int srow = tid >> 3, skc = tid & 7;   // rows srow, srow+64 per array

    auto stage = [&](int t, int buf) {
        int k0 = t << 6;
        uint32_t sb = sbase + (uint32_t)buf * 65536u;
        #pragma unroll
        for (int i = 0; i < 2; i++) {
            int row = srow + i * 64;
            uint32_t soff = (uint32_t)row * 128 + (uint32_t)((skc ^ (row & 7)) << 4);
            size_t ao = (size_t)(m0 + row) * lda + k0 + skc * 8;
            size_t bo = (size_t)(n0 + row) * ldb + k0 + skc * 8;
            cp16(sb + soff,          AH + ao);
            cp16(sb + 16384 + soff,  AL + ao);
            cp16(sb + 32768 + soff,  BH + bo);
            cp16(sb + 49152 + soff,  BL + bo);
        }
        asm volatile("cp.async.commit_group;\n" ::: "memory");
    };

    stage(0, 0);
    if (ktiles > 1) stage(1, 1);
    int bt = 0;
    for (int t = 0; t < ktiles; t++) {
        asm volatile("cp.async.wait_group 1;\n" ::: "memory");   // tile t resident
        __syncthreads();
        if (t + 2 < ktiles) {
            int nb = bt + 2;
            if (nb >= 3) nb -= 3;
            stage(t + 2, nb);
        }

        uint32_t aHb = sbase + (uint32_t)bt * 65536u;
        uint32_t aLb = aHb + 16384, bHb = aHb + 32768, bLb = aHb + 49152;
        #pragma unroll
        for (int ks = 0; ks < 4; ks++) {
            uint32_t ah[2][4], al[2][4];
            #pragma unroll
            for (int mi = 0; mi < 2; mi++) {
                int row = wm + mi * 16 + (lane & 15);
                int c = ks * 2 + (lane >> 4);
                uint32_t off = (uint32_t)row * 128 + (uint32_t)((c ^ (row & 7)) << 4);
                ldsm4(ah[mi], aHb + off);
                ldsm4(al[mi], aLb + off);
            }
            #pragma unroll
            for (int np = 0; np < 2; np++) {
                uint32_t bh[4], bl[4];
                int row = wn + np * 16 + (lane & 15);
                int c = ks * 2 + (lane >> 4);
                uint32_t off = (uint32_t)row * 128 + (uint32_t)((c ^ (row & 7)) << 4);
                ldsm4(bh, bHb + off);
                ldsm4(bl, bLb + off);
                #pragma unroll
                for (int mi = 0; mi < 2; mi++) {
                    mma16816(acc[mi][2 * np],     ah[mi], bh[0], bh[2]);
                    mma16816(acc[mi][2 * np],     al[mi], bh[0], bh[2]);
                    mma16816(acc[mi][2 * np],     ah[mi], bl[0], bl[2]);
                    mma16816(acc[mi][2 * np + 1], ah[mi], bh[1], bh[3]);
                    mma16816(acc[mi][2 * np + 1], al[mi], bh[1], bh[3]);
                    mma16816(acc[mi][2 * np + 1], ah[mi], bl[1], bl[3]);
                }
            }
        }
        bt = (bt + 1 == 3) ? 0 : bt + 1;
    }

    // ---- epilogue ----
    int gid = lane >> 2, tig = lane & 3;
    #pragma unroll
    for (int mi = 0; mi < 2; mi++) {
        #pragma unroll
        for (int ni = 0; ni < 4; ni++) {
            int row = m0 + wm + mi * 16 + gid;
            int col = n0 + wn + ni * 8 + tig * 2;
            if (col + 1 < N && row < M) {
                float* cp = &C[(size_t)row * N + col];
                float2 v = make_float2(acc[mi][ni][0], acc[mi][ni][1]);
                if (addC) { float2 o = *(float2*)cp; v.x += o.x; v.y += o.y; }
                *(float2*)cp = v;
                float* cp8 = cp + 8 * (size_t)N;
                float2 w = make_float2(acc[mi][ni][2], acc[mi][ni][3]);
                if (addC) { float2 o = *(float2*)cp8; w.x += o.x; w.y += o.y; }
                *(float2*)cp8 = w;
            }
        }
    }
}

// ---------------- embeddings ----------------
__global__ void embed_img_kernel(const int* __restrict__ ids, const float* __restrict__ te,
                                 const float* __restrict__ pe, float* __restrict__ out) {
    int i = blockIdx.x * blockDim.x + threadIdx.x;
    if (i >= NTOK * DMODEL) return;
    int n = i >> 10, d = i & 1023;
    out[i] = te[(size_t)ids[n] * DMODEL + d] + pe[i];
}
__global__ void embed_ctx_kernel(const int* __restrict__ ids, const float* __restrict__ te,
                                 const float* __restrict__ pe,
                                 __nv_bfloat16* __restrict__ Yh, __nv_bfloat16* __restrict__ Yl) {
    int p = blockIdx.x * blockDim.x + threadIdx.x;
    if (p >= NCTX * DMODEL / 2) return;
    int i = p * 2;
    int n = i >> 10, d = i & 1023;
    const float* row = te + (size_t)ids[n] * DMODEL;
    float f0 = row[d] + pe[i];
    float f1 = row[d + 1] + pe[i + 1];
    uint32_t hi, lo;
    split2(f0, f1, hi, lo);
    *(uint32_t*)&Yh[i] = hi;
    *(uint32_t*)&Yl[i] = lo;
}

// ---------------- LayerNorm -> bf16 hi/lo (C = 1024 fixed) ----------------
__global__ void ln_kernel(const float* __restrict__ X, const float* __restrict__ g,
                          __nv_bfloat16* __restrict__ Yh, __nv_bfloat16* __restrict__ Yl) {
    int row = blockIdx.x;
    const float* x = X + (size_t)row * DMODEL;
    int tid = threadIdx.x;
    float v[4], s1 = 0.f, s2 = 0.f;
    #pragma unroll
    for (int j = 0; j < 4; j++) { v[j] = x[tid * 4 + j]; s1 += v[j]; s2 += v[j] * v[j]; }
    __shared__ float red[512];
    red[tid] = s1; red[256 + tid] = s2;
    __syncthreads();
    for (int s = 128; s > 0; s >>= 1) {
        if (tid < s) { red[tid] += red[tid + s]; red[256 + tid] += red[256 + tid + s]; }
        __syncthreads();
    }
    float mean = red[0] / DMODEL;
    float var  = red[256] / DMODEL - mean * mean;
    float inv  = rsqrtf(var + 1e-5f);
    float y[4];
    #pragma unroll
    for (int j = 0; j < 4; j++) y[j] = (v[j] - mean) * inv * g[tid * 4 + j];
    uint32_t h0, l0, h1, l1;
    split2(y[0], y[1], h0, l0);
    split2(y[2], y[3], h1, l1);
    size_t o = (size_t)row * DMODEL + tid * 4;
    *(uint2*)&Yh[o] = make_uint2(h0, h1);
    *(uint2*)&Yl[o] = make_uint2(l0, l1);
}

// ---------------- fused GEGLU + LayerNorm -> bf16 hi/lo [row][FFIP] ----------------
__global__ void geglu_ln_kernel(const float* __restrict__ HH, const float* __restrict__ g2,
                                __nv_bfloat16* __restrict__ Yh, __nv_bfloat16* __restrict__ Yl) {
    int row = blockIdx.x;
    const float* h = HH + (size_t)row * FF2;
    int tid = threadIdx.x;
    __shared__ float buf[FFI];
    __shared__ float red[512];
    float s1 = 0.f, s2 = 0.f;
    for (int c = tid; c < FFI; c += 256) {
        float a = h[c], gate = h[FFI + c];
        float v = gate * (0.5f * a * (1.0f + erff(a * 0.70710678118654752f)));
        buf[c] = v; s1 += v; s2 += v * v;
    }
    red[tid] = s1; red[256 + tid] = s2;
    __syncthreads();
    for (int s = 128; s > 0; s >>= 1) {
        if (tid < s) { red[tid] += red[tid + s]; red[256 + tid] += red[256 + tid + s]; }
        __syncthreads();
    }
    float mean = red[0] / FFI;
    float var  = red[256] / FFI - mean * mean;
    float inv  = rsqrtf(var + 1e-5f);
    for (int q = tid; q < FFIP / 4; q += 256) {
        int c = q * 4;
        float y[4];
        #pragma unroll
        for (int j = 0; j < 4; j++) {
            int cc = c + j;
            y[j] = (cc < FFI) ? (buf[cc] - mean) * inv * g2[cc] : 0.f;
        }
        uint32_t h0, l0, h1, l1;
        split2(y[0], y[1], h0, l0);
        split2(y[2], y[3], h1, l1);
        size_t o = (size_t)row * FFIP + c;
        *(uint2*)&Yh[o] = make_uint2(h0, h1);
        *(uint2*)&Yl[o] = make_uint2(l0, l1);
    }
}

// ---------------- Q prep (stride-parameterized source) ----------------
__global__ void prep_q_kernel(const float* __restrict__ Qin, const float* __restrict__ qs,
                              float* __restrict__ QN, int Nq, int srcStride) {
    int gw = (blockIdx.x * blockDim.x + threadIdx.x) >> 5;
    int lane = threadIdx.x & 31;
    if (gw >= NHEAD * Nq) return;
    int h = gw / Nq, n = gw % Nq;
    const float* src = Qin + (size_t)n * srcStride + h * DHEAD;
    float v0 = src[lane], v1 = src[lane + 32];
    float ss = v0 * v0 + v1 * v1;
    #pragma unroll
    for (int s = 16; s; s >>= 1) ss += __shfl_xor_sync(0xffffffffu, ss, s);
    float inv = 1.0f / fmaxf(sqrtf(ss), 1e-12f);
    float* dst = QN + ((size_t)h * Nq + n) * DHEAD;
    dst[lane]      = v0 * inv * qs[lane] * 8.0f;
    dst[lane + 32] = v1 * inv * qs[lane + 32] * 8.0f;
}

// ---------------- KV prep (stride + v-offset parameterized) ----------------
__global__ void prep_kv_kernel(const float* __restrict__ KVin, const float* __restrict__ nullp,
                               const float* __restrict__ ks, float* __restrict__ Ko,
                               float* __restrict__ Vo, int Nt, int srcStride, int vOff) {
    int NK = Nt + 1;
    int gw = (blockIdx.x * blockDim.x + threadIdx.x) >> 5;
    int lane = threadIdx.x & 31;
    if (gw >= NHEAD * NK) return;
    int h = gw / NK, j = gw % NK;
    float k0, k1, v0, v1;
    if (j == 0) {
        k0 = nullp[h * DHEAD + lane];
        k1 = nullp[h * DHEAD + lane + 32];
        v0 = nullp[NHEAD * DHEAD + h * DHEAD + lane];
        v1 = nullp[NHEAD * DHEAD + h * DHEAD + lane + 32];
    } else {
        const float* src = KVin + (size_t)(j - 1) * srcStride + h * DHEAD;
        k0 = src[lane];          k1 = src[lane + 32];
        v0 = src[vOff + lane];   v1 = src[vOff + lane + 32];
    }
    float ss = k0 * k0 + k1 * k1;
    #pragma unroll
    for (int s = 16; s; s >>= 1) ss += __shfl_xor_sync(0xffffffffu, ss, s);
    float inv = 1.0f / fmaxf(sqrtf(ss), 1e-12f);
    size_t base = ((size_t)h * NK + j) * DHEAD;
    Ko[base + lane]      = k0 * inv * ks[lane];
    Ko[base + lane + 32] = k1 * inv * ks[lane + 32];
    Vo[base + lane]      = v0;
    Vo[base + lane + 32] = v1;
}

// ---------------- fused flash attention (scalar; epilogue emits bf16 hi/lo) ----------------
__global__ __launch_bounds__(256, 2)
void flash_kernel(const float* __restrict__ Q, const float* __restrict__ K,
                  const float* __restrict__ V,
                  __nv_bfloat16* __restrict__ Oh, __nv_bfloat16* __restrict__ Ol,
                  int Nq, int NK) {
    extern __shared__ float sm[];
    float* Qs = sm;
    float* KT = sm + 8192;
    float* Ps = sm + 12288;
    int h  = blockIdx.y;
    int qb = blockIdx.x * 128;
    int tid = threadIdx.x;
    int tx = tid & 15, ty = tid >> 4;
    int r0 = ty * 8, c0 = tx * 4;

    const float* Qg = Q + ((size_t)h * Nq + qb) * DHEAD;
    for (int i = tid * 4; i < 8192; i += 1024)
        *(float4*)&Qs[i] = *(const float4*)&Qg[i];

    float o[8][4];
    float mrow[8], lrow[8];
    #pragma unroll
    for (int i = 0; i < 8; i++) {
        mrow[i] = -1e30f; lrow[i] = 0.f;
        o[i][0] = o[i][1] = o[i][2] = o[i][3] = 0.f;
    }

    int ntiles = (NK + 63) >> 6;
    int kj = tid & 63, kd = (tid >> 6) << 4;

    for (int t = 0; t < ntiles; t++) {
        int kb = t << 6;
        __syncthreads();
        {
            bool valid = (kb + kj) < NK;
            const float* Kg = K + ((size_t)h * NK + kb + kj) * DHEAD;
            #pragma unroll
            for (int r = 0; r < 4; r++) {
                int d0 = kd + r * 4;
                float4 g = valid ? *(const float4*)&Kg[d0] : make_float4(0, 0, 0, 0);
                KT[(d0 + 0) * 64 + kj] = g.x;
                KT[(d0 + 1) * 64 + kj] = g.y;
                KT[(d0 + 2) * 64 + kj] = g.z;
                KT[(d0 + 3) * 64 + kj] = g.w;
            }
        }
        __syncthreads();

        float acc[8][4];
        #pragma unroll
        for (int i = 0; i < 8; i++) acc[i][0] = acc[i][1] = acc[i][2] = acc[i][3] = 0.f;
        #pragma unroll
        for (int d = 0; d < 64; d += 4) {
            float4 k4[4];
            #pragma unroll
            for (int j = 0; j < 4; j++) k4[j] = *(float4*)&KT[(d + j) * 64 + c0];
            #pragma unroll
            for (int i = 0; i < 8; i++) {
                float4 q4 = *(float4*)&Qs[(r0 + i) * 64 + d];
                acc[i][0] += q4.x * k4[0].x + q4.y * k4[1].x + q4.z * k4[2].x + q4.w * k4[3].x;
                acc[i][1] += q4.x * k4[0].y + q4.y * k4[1].y + q4.z * k4[2].y + q4.w * k4[3].y;
                acc[i][2] += q4.x * k4[0].z + q4.y * k4[1].z + q4.z * k4[2].z + q4.w * k4[3].z;
                acc[i][3] += q4.x * k4[0].w + q4.y * k4[1].w + q4.z * k4[2].w + q4.w * k4[3].w;
            }
        }
        if (kb + 64 > NK) {
            #pragma unroll
            for (int j = 0; j < 4; j++)
                if (kb + c0 + j >= NK)
                    #pragma unroll
                    for (int i = 0; i < 8; i++) acc[i][j] = -1e30f;
        }
        float tmax[8];
        #pragma unroll
        for (int i = 0; i < 8; i++)
            tmax[i] = fmaxf(fmaxf(acc[i][0], acc[i][1]), fmaxf(acc[i][2], acc[i][3]));
        #pragma unroll
        for (int s = 1; s < 16; s <<= 1)
            #pragma unroll
            for (int i = 0; i < 8; i++)
                tmax[i] = fmaxf(tmax[i], __shfl_xor_sync(0xffffffffu, tmax[i], s, 32));
        float corr[8];
        #pragma unroll
        for (int i = 0; i < 8; i++) {
            float mnew = fmaxf(mrow[i], tmax[i]);
            corr[i] = expf(mrow[i] - mnew);
            mrow[i] = mnew;
        }
        float rsum[8];
        #pragma unroll
        for (int i = 0; i < 8; i++) {
            float s = 0.f;
            #pragma unroll
            for (int j = 0; j < 4; j++) {
                float p = expf(acc[i][j] - mrow[i]);
                acc[i][j] = p; s += p;
            }
            rsum[i] = s;
        }
        #pragma unroll
        for (int s = 1; s < 16; s <<= 1)
            #pragma unroll
            for (int i = 0; i < 8; i++)
                rsum[i] += __shfl_xor_sync(0xffffffffu, rsum[i], s, 32);
        #pragma unroll
        for (int i = 0; i < 8; i++) {
            lrow[i] = lrow[i] * corr[i] + rsum[i];
            o[i][0] *= corr[i]; o[i][1] *= corr[i]; o[i][2] *= corr[i]; o[i][3] *= corr[i];
            *(float4*)&Ps[(r0 + i) * 64 + c0] = make_float4(acc[i][0], acc[i][1], acc[i][2], acc[i][3]);
        }
        __syncthreads();
        for (int i = tid * 4; i < 4096; i += 1024) {
            int j = i >> 6;
            *(float4*)&KT[i] = (kb + j < NK)
                ? *(const float4*)&V[((size_t)h * NK + kb + j) * DHEAD + (i & 63)]
                : make_float4(0, 0, 0, 0);
        }
        __syncthreads();
        #pragma unroll
        for (int jk = 0; jk < 64; jk += 4) {
            float4 v4[4];
            #pragma unroll
            for (int jj = 0; jj < 4; jj++) v4[jj] = *(float4*)&KT[(jk + jj) * 64 + c0];
            #pragma unroll
            for (int i = 0; i < 8; i++) {
                float4 p4 = *(float4*)&Ps[(r0 + i) * 64 + jk];
                o[i][0] += p4.x * v4[0].x + p4.y * v4[1].x + p4.z * v4[2].x + p4.w * v4[3].x;
                o[i][1] += p4.x * v4[0].y + p4.y * v4[1].y + p4.z * v4[2].y + p4.w * v4[3].y;
                o[i][2] += p4.x * v4[0].z + p4.y * v4[1].z + p4.z * v4[2].z + p4.w * v4[3].z;
                o[i][3] += p4.x * v4[0].w + p4.y * v4[1].w + p4.z * v4[2].w + p4.w * v4[3].w;
            }
        }
    }
    #pragma unroll
    for (int i = 0; i < 8; i++) {
        float inv = 1.f / lrow[i];
        int n = qb + r0 + i;
        uint32_t h0, l0, h1, l1;
        split2(o[i][0] * inv, o[i][1] * inv, h0, l0);
        split2(o[i][2] * inv, o[i][3] * inv, h1, l1);
        size_t off = (size_t)n * DMODEL + h * DHEAD + c0;
        *(uint2*)&Oh[off] = make_uint2(h0, h1);
        *(uint2*)&Ol[off] = make_uint2(l0, l1);
    }
}

// ---------------- host orchestration ----------------
extern "C" void kernel_launch(void* const* d_in, const int* in_sizes, int n_in,
                              void* d_out, int out_size) {
    (void)in_sizes; (void)n_in; (void)out_size;
    const int*   x_ids    = (const int*)d_in[0];
    const int*   cond_ids = (const int*)d_in[1];
    const float* token_emb = (const float*)d_in[2];
    const float* pos_emb   = (const float*)d_in[3];
    const float* cte       = (const float*)d_in[4];
    const float* cpe       = (const float*)d_in[5];
    const float* sa_g    = (const float*)d_in[6];
    const float* sa_wq   = (const float*)d_in[7];
    const float* sa_wkv  = (const float*)d_in[8];
    const float* sa_null = (const float*)d_in[9];
    const float* sa_qs   = (const float*)d_in[10];
    const float* sa_ks   = (const float*)d_in[11];
    const float* sa_wo   = (const float*)d_in[12];
    const float* ca_g    = (const float*)d_in[13];
    const float* ca_wq   = (const float*)d_in[14];
    const float* ca_wkv  = (const float*)d_in[15];
    const float* ca_null = (const float*)d_in[16];
    const float* ca_qs   = (const float*)d_in[17];
    const float* ca_ks   = (const float*)d_in[18];
    const float* ca_wo   = (const float*)d_in[19];
    const float* ff_g1   = (const float*)d_in[20];
    const float* ff_w1   = (const float*)d_in[21];
    const float* ff_g2   = (const float*)d_in[22];
    const float* ff_w2   = (const float*)d_in[23];
    const float* final_g  = (const float*)d_in[24];
    const float* w_logits = (const float*)d_in[25];
    float* out = (float*)d_out;

    float *H, *QKV, *Q, *KV, *QN, *K, *V, *HH;
    __nv_bfloat16 *WH, *WL, *XNh, *XNl, *CTXh, *CTXl, *Oh, *Ol, *GNh, *GNl;
    cudaGetSymbolAddress((void**)&H,   g_H);
    cudaGetSymbolAddress((void**)&QKV, g_QKV);
    cudaGetSymbolAddress((void**)&Q,   g_Q);
    cudaGetSymbolAddress((void**)&KV,  g_KV);
    cudaGetSymbolAddress((void**)&QN,  g_QN);
    cudaGetSymbolAddress((void**)&K,   g_K);
    cudaGetSymbolAddress((void**)&V,   g_V);
    cudaGetSymbolAddress((void**)&HH,  g_HH);
    cudaGetSymbolAddress((void**)&WH,  g_WH);
    cudaGetSymbolAddress((void**)&WL,  g_WL);
    cudaGetSymbolAddress((void**)&XNh, g_XNh);
    cudaGetSymbolAddress((void**)&XNl, g_XNl);
    cudaGetSymbolAddress((void**)&CTXh, g_CTXh);
    cudaGetSymbolAddress((void**)&CTXl, g_CTXl);
    cudaGetSymbolAddress((void**)&Oh,  g_Oh);
    cudaGetSymbolAddress((void**)&Ol,  g_Ol);
    cudaGetSymbolAddress((void**)&GNh, g_GNh);
    cudaGetSymbolAddress((void**)&GNl, g_GNl);

    const int FLASH_SMEM = 20480 * 4;    // 80KB
    const int GEMM_SMEM  = 196608;       // 192KB (3 x 64KB ring)
    cudaFuncSetAttribute(flash_kernel, cudaFuncAttributeMaxDynamicSharedMemorySize, FLASH_SMEM);
    cudaFuncSetAttribute(gemm_bf16_kernel, cudaFuncAttributeMaxDynamicSharedMemorySize, GEMM_SMEM);

    // ---- fused weight conversion: one launch for all 33 weights ----
    {
        ConvTab tab;
        int cnt = 0, tiles = 0;
        auto add = [&](const float* W, long long off, int Kd, int Nd, int k_pad, int n_pad) {
            ConvEnt& e = tab.e[cnt++];
            e.W = W; e.off = off; e.K = Kd; e.N = Nd; e.kpad = k_pad;
            e.tiles_n = n_pad / 32; e.tileStart = tiles;
            tiles += (n_pad / 32) * (k_pad / 32);
        };
        for (int l = 0; l < NLAYER; l++) {
            long long lb = (long long)l * LBLK;
            add(sa_wq  + (size_t)l * DMODEL * DMODEL,     lb + W_WQ,   1024, 1024, 1024, 1024);
            add(sa_wkv + (size_t)l * DMODEL * 2 * DMODEL, lb + W_WKV,  1024, 2048, 1024, 2048);
            add(sa_wo  + (size_t)l * DMODEL * DMODEL,     lb + W_WO,   1024, 1024, 1024, 1024);
            add(ca_wq  + (size_t)l * DMODEL * DMODEL,     lb + W_CWQ,  1024, 1024, 1024, 1024);
            add(ca_wkv + (size_t)l * DMODEL * 2 * DMODEL, lb + W_CWKV, 1024, 2048, 1024, 2048);
            add(ca_wo  + (size_t)l * DMODEL * DMODEL,     lb + W_CWO,  1024, 1024, 1024, 1024);
            add(ff_w1  + (size_t)l * DMODEL * FF2,        lb + W_FF1,  1024, FF2,  1024, 5504);
            add(ff_w2  + (size_t)l * FFI * DMODEL,        lb + W_FF2,  FFI,  1024, FFIP, 1024);
        }
        add(w_logits, W_LOG, 1024, VOCAB, 1024, VOCAB);
        tab.cnt = cnt;
        convw_all_kernel<<<tiles, 256>>>(tab, WH, WL);
    }

    embed_img_kernel<<<(NTOK * DMODEL) / 256, 256>>>(x_ids, token_emb, pos_emb, H);
    embed_ctx_kernel<<<(NCTX * DMODEL / 2) / 256, 256>>>(cond_ids, cte, cpe, CTXh, CTXl);

    auto gemm = [&](const __nv_bfloat16* aH, const __nv_bfloat16* aL, size_t woff,
                    float* Cp, int M, int N, int lda, int ldb, int ktiles, int addC,
                    int gx, int gy) {
        gemm_bf16_kernel<<<dim3(gx, gy), 512, GEMM_SMEM>>>(aH, aL, WH + woff, WL + woff,
                                                           Cp, M, N, lda, ldb, ktiles, addC);
    };

    for (int l = 0; l < NLAYER; l++) {
        size_t lb = (size_t)l * LBLK;
        // ------- self attention (fused QKV projection: N = 3072) -------
        ln_kernel<<<NTOK, 256>>>(H, sa_g + (size_t)l * DMODEL, XNh, XNl);
        gemm(XNh, XNl, lb + W_WQ, QKV, NTOK, 3072, 1024, 1024, 16, 0, 24, 12);
        prep_q_kernel<<<(NHEAD * NTOK + 7) / 8, 256>>>(QKV, sa_qs + l * DHEAD, QN, NTOK, 3072);
        prep_kv_kernel<<<(NHEAD * (NTOK + 1) + 7) / 8, 256>>>(QKV + DMODEL,
                                                              sa_null + (size_t)l * 2 * NHEAD * DHEAD,
                                                              sa_ks + l * DHEAD, K, V, NTOK, 3072, DMODEL);
        flash_kernel<<<dim3(NTOK / 128, NHEAD), 256, FLASH_SMEM>>>(QN, K, V, Oh, Ol, NTOK, NTOK + 1);
        gemm(Oh, Ol, lb + W_WO, H, NTOK, 1024, 1024, 1024, 16, 1, 8, 12);

        // ------- cross attention -------
        ln_kernel<<<NTOK, 256>>>(H, ca_g + (size_t)l * DMODEL, XNh, XNl);
        gemm(XNh, XNl, lb + W_CWQ, Q, NTOK, 1024, 1024, 1024, 16, 0, 8, 12);
        gemm(CTXh, CTXl, lb + W_CWKV, KV, NCTX, 2048, 1024, 1024, 16, 0, 16, 4);
        prep_q_kernel<<<(NHEAD * NTOK + 7) / 8, 256>>>(Q, ca_qs + l * DHEAD, QN, NTOK, DMODEL);
        prep_kv_kernel<<<(NHEAD * (NCTX + 1) + 7) / 8, 256>>>(KV, ca_null + (size_t)l * 2 * NHEAD * DHEAD,
                                                              ca_ks + l * DHEAD, K, V, NCTX,
                                                              2 * DMODEL, DMODEL);
        flash_kernel<<<dim3(NTOK / 128, NHEAD), 256, FLASH_SMEM>>>(QN, K, V, Oh, Ol, NTOK, NCTX + 1);
        gemm(Oh, Ol, lb + W_CWO, H, NTOK, 1024, 1024, 1024, 16, 1, 8, 12);

        // ------- GEGLU feedforward -------
        ln_kernel<<<NTOK, 256>>>(H, ff_g1 + (size_t)l * DMODEL, XNh, XNl);
        gemm(XNh, XNl, lb + W_FF1, HH, NTOK, FF2, 1024, 1024, 16, 0, 43, 12);
        geglu_ln_kernel<<<NTOK, 256>>>(HH, ff_g2 + (size_t)l * FFI, GNh, GNl);
        gemm(GNh, GNl, lb + W_FF2, H, NTOK, 1024, FFIP, FFIP, 43, 1, 8, 12);
    }

    // ------- final norm + logits -------
    ln_kernel<<<NTOK, 256>>>(H, final_g, XNh, XNl);
    gemm(XNh, XNl, W_LOG, out, NTOK, VOCAB, 1024, 1024, 16, 0, 64, 12);
}